// round 9
// baseline (speedup 1.0000x reference)
#include <cuda_runtime.h>
#include <math.h>

#define TT   2048
#define DD   2048
#define HQn  16
#define HKVn 8
#define HDn  128
#define En   16
#define Fn   1024
#define FSn  2048
#define NQKV 4096
#define PAIRS (TT*2)

__device__ float g_xn[(size_t)TT*DD];
__device__ float g_qkv[(size_t)TT*NQKV];
__device__ float g_attn[(size_t)TT*DD];
__device__ float g_x2[(size_t)TT*DD];
__device__ float g_h[(size_t)TT*DD];
__device__ float g_s1[(size_t)TT*FSn];
__device__ float g_s3[(size_t)TT*FSn];
__device__ float g_sharedY[(size_t)TT*DD];
__device__ float g_gbuf[(size_t)PAIRS*Fn];
__device__ float g_ubuf[(size_t)PAIRS*Fn];
__device__ float g_y[(size_t)PAIRS*DD];
__device__ float g_k2[(size_t)TT*HKVn*HDn];   // roped K, fresh layout [t][kvh][d]
__device__ int   g_idx[PAIRS];
__device__ float g_wtk[PAIRS];
__device__ int   g_cnt[En];
__device__ int   g_off[En];
__device__ int   g_cur[En];
__device__ int   g_perm[PAIRS];

__device__ __forceinline__ float siluf(float x) { return x / (1.f + expf(-x)); }

// fresh RoPE helper: pair index i (0..63), token t. Returns cos/sin.
__device__ __forceinline__ void rope_cs(const int* __restrict__ p32, int t, int i,
                                        float& c, float& s) {
    int sec = (i < 22) ? 0 : ((i < 44) ? 1 : 2);
    bool is64 = (p32[1] == 0);
    int lin = sec * TT + t;
    float pos = (float)(is64 ? p32[2*lin] : p32[lin]);
    float invf = (float)exp(-((double)i / 64.0) * log(500000.0));
    sincosf(pos * invf, &s, &c);
}

#define MICROTILE_STEP(As, Bs, kk, acc) do { \
    float4 a0 = *(const float4*)&As[kk][ty*8];   \
    float4 a1 = *(const float4*)&As[kk][ty*8+4]; \
    float4 b0 = *(const float4*)&Bs[kk][tx*8];   \
    float4 b1 = *(const float4*)&Bs[kk][tx*8+4]; \
    float ra[8] = {a0.x,a0.y,a0.z,a0.w,a1.x,a1.y,a1.z,a1.w}; \
    float rb[8] = {b0.x,b0.y,b0.z,b0.w,b1.x,b1.y,b1.z,b1.w}; \
    _Pragma("unroll") for (int i_ = 0; i_ < 8; i_++) \
      _Pragma("unroll") for (int j_ = 0; j_ < 8; j_++) \
        acc[i_][j_] = fmaf(ra[i_], rb[j_], acc[i_][j_]); \
} while (0)

__global__ void rmsnorm_kernel(const float* __restrict__ x, const float* __restrict__ w,
                               float* __restrict__ out) {
    int row = blockIdx.x;
    const float* xr = x + (size_t)row * DD;
    float* orow = out + (size_t)row * DD;
    float sum = 0.f;
    for (int i = threadIdx.x; i < DD; i += 256) { float v = xr[i]; sum = fmaf(v, v, sum); }
    __shared__ float red[8]; __shared__ float rinv;
    for (int o = 16; o > 0; o >>= 1) sum += __shfl_xor_sync(0xffffffffu, sum, o);
    if ((threadIdx.x & 31) == 0) red[threadIdx.x >> 5] = sum;
    __syncthreads();
    if (threadIdx.x == 0) {
        float s = 0.f;
        #pragma unroll
        for (int i = 0; i < 8; i++) s += red[i];
        rinv = rsqrtf(s / (float)DD + 1e-5f);
    }
    __syncthreads();
    float r = rinv;
    for (int i = threadIdx.x; i < DD; i += 256) orow[i] = xr[i] * r * w[i];
}

// ---------- fresh naive QKV GEMM: C[t,n] = sum_k xn[t,k] * wqkv[k,n] ----------
__global__ void qkv_naive_kernel(const float* __restrict__ A, const float* __restrict__ B,
                                 float* __restrict__ C) {
    __shared__ float As[16][17];
    __shared__ float Bs[16][17];
    int tx = threadIdx.x, ty = threadIdx.y;
    int row = blockIdx.y * 16 + ty;
    int col = blockIdx.x * 16 + tx;
    float acc = 0.f;
    for (int kt = 0; kt < DD; kt += 16) {
        As[ty][tx] = A[(size_t)row * DD + kt + tx];
        Bs[ty][tx] = B[(size_t)(kt + ty) * NQKV + col];
        __syncthreads();
        #pragma unroll
        for (int j = 0; j < 16; j++) acc = fmaf(As[ty][j], Bs[j][tx], acc);
        __syncthreads();
    }
    C[(size_t)row * NQKV + col] = acc;
}

// ---------- fresh out-of-place K rope: g_k2[t][kh][d] ----------
__global__ void ropek_kernel(const float* __restrict__ qkv, const int* __restrict__ p32) {
    int t = blockIdx.x, kh = blockIdx.y, i = threadIdx.x;   // i = pair 0..63
    const float* src = qkv + (size_t)t * NQKV + HQn*HDn + kh * HDn;
    float c, s;
    rope_cs(p32, t, i, c, s);
    float x1 = src[2*i], x2 = src[2*i+1];
    float* dst = g_k2 + ((size_t)t * HKVn + kh) * HDn;
    dst[2*i]   = x1 * c - x2 * s;
    dst[2*i+1] = x2 * c + x1 * s;
}

// ---------- fused brute-force attention: one block per (q, h) ----------
__global__ void __launch_bounds__(256) attn_fused_kernel(const float* __restrict__ qkv,
                                                         const int* __restrict__ p32,
                                                         float* __restrict__ attn) {
    int q = blockIdx.x, h = blockIdx.y;
    const int L = q + 1;
    const int kvh = h >> 1;
    const int tid = threadIdx.x;
    __shared__ float qs[HDn];
    __shared__ float sc[TT];
    __shared__ float red[8];
    __shared__ float bc;
    __shared__ float osum[256];
    const float scale = 0.08838834764831845f;   // 1/sqrt(128)

    // rope q inline (fresh), pre-scaled
    if (tid < 64) {
        const float* src = qkv + (size_t)q * NQKV + h * HDn;
        float c, s;
        rope_cs(p32, q, tid, c, s);
        float x1 = src[2*tid], x2 = src[2*tid+1];
        qs[2*tid]   = (x1 * c - x2 * s) * scale;
        qs[2*tid+1] = (x2 * c + x1 * s) * scale;
    }
    __syncthreads();

    // scores vs all k <= q
    for (int k = tid; k < L; k += 256) {
        const float* kp = g_k2 + ((size_t)k * HKVn + kvh) * HDn;
        float acc = 0.f;
        #pragma unroll 8
        for (int d = 0; d < HDn; d++) acc = fmaf(qs[d], kp[d], acc);
        sc[k] = acc;
    }
    __syncthreads();

    // softmax over sc[0..L-1]
    float mx = -INFINITY;
    for (int k = tid; k < L; k += 256) mx = fmaxf(mx, sc[k]);
    for (int o = 16; o > 0; o >>= 1) mx = fmaxf(mx, __shfl_xor_sync(0xffffffffu, mx, o));
    if ((tid & 31) == 0) red[tid >> 5] = mx;
    __syncthreads();
    if (tid == 0) {
        float m = red[0];
        #pragma unroll
        for (int i = 1; i < 8; i++) m = fmaxf(m, red[i]);
        bc = m;
    }
    __syncthreads();
    mx = bc;
    float sum = 0.f;
    for (int k = tid; k < L; k += 256) {
        float p = expf(sc[k] - mx);
        sc[k] = p;
        sum += p;
    }
    for (int o = 16; o > 0; o >>= 1) sum += __shfl_xor_sync(0xffffffffu, sum, o);
    if ((tid & 31) == 0) red[tid >> 5] = sum;
    __syncthreads();
    if (tid == 0) {
        float s = 0.f;
        #pragma unroll
        for (int i = 0; i < 8; i++) s += red[i];
        bc = 1.f / s;
    }
    __syncthreads();
    float inv = bc;

    // o[d] = sum_k p[k] * v[k][d]; 2 threads per d
    int d = tid & 127, half = tid >> 7;
    float o = 0.f;
    for (int k = half; k < L; k += 2)
        o = fmaf(sc[k], qkv[(size_t)k * NQKV + HQn*HDn + HKVn*HDn + kvh*HDn + d], o);
    osum[half * 128 + d] = o;
    __syncthreads();
    if (tid < 128)
        attn[(size_t)q * DD + h * HDn + tid] = (osum[tid] + osum[128 + tid]) * inv;
}

__global__ void __launch_bounds__(256) sgemm_kernel(
    const float* __restrict__ A, const float* __restrict__ B,
    float* __restrict__ C, const float* __restrict__ resid,
    int N, int K) {
    __shared__ float As[8][128];
    __shared__ float Bs[8][128];
    const int tid = threadIdx.x;
    const int tx = tid & 15, ty = tid >> 4;
    const int bx = blockIdx.x * 128, by = blockIdx.y * 128;
    const int aRow = tid >> 1, aCol = (tid & 1) << 2;
    const int bRow = tid >> 5, bCol = (tid & 31) << 2;
    const float* Aptr = A + (size_t)(by + aRow) * K + aCol;
    const float* Bptr = B + (size_t)bRow * N + bx + bCol;
    float acc[8][8];
    #pragma unroll
    for (int i = 0; i < 8; i++)
        #pragma unroll
        for (int j = 0; j < 8; j++) acc[i][j] = 0.f;
    for (int k0 = 0; k0 < K; k0 += 8) {
        float4 a4 = *(const float4*)(Aptr + k0);
        float4 b4 = *(const float4*)(Bptr + (size_t)k0 * N);
        As[aCol+0][aRow] = a4.x; As[aCol+1][aRow] = a4.y;
        As[aCol+2][aRow] = a4.z; As[aCol+3][aRow] = a4.w;
        *(float4*)&Bs[bRow][bCol] = b4;
        __syncthreads();
        #pragma unroll
        for (int kk = 0; kk < 8; kk++) MICROTILE_STEP(As, Bs, kk, acc);
        __syncthreads();
    }
    #pragma unroll
    for (int i = 0; i < 8; i++) {
        size_t r = (size_t)(by + ty*8 + i);
        float* Cp = C + r * N + bx + tx*8;
        float4 c0 = make_float4(acc[i][0],acc[i][1],acc[i][2],acc[i][3]);
        float4 c1 = make_float4(acc[i][4],acc[i][5],acc[i][6],acc[i][7]);
        if (resid) {
            const float* Rp = resid + r * N + bx + tx*8;
            float4 r0 = *(const float4*)Rp; float4 r1 = *(const float4*)(Rp+4);
            c0.x += r0.x; c0.y += r0.y; c0.z += r0.z; c0.w += r0.w;
            c1.x += r1.x; c1.y += r1.y; c1.z += r1.z; c1.w += r1.w;
        }
        *(float4*)Cp = c0; *(float4*)(Cp+4) = c1;
    }
}

__global__ void zero_cnt_kernel() { if (threadIdx.x < En) g_cnt[threadIdx.x] = 0; }

__global__ void gate_route_kernel(const float* __restrict__ gw, const float* __restrict__ gbias) {
    int t = blockIdx.x, tid = threadIdx.x;
    const float* hr = g_h + (size_t)t * DD;
    __shared__ float part[128];
    __shared__ float lg[En];
    int e = tid & 15, gdx = tid >> 4;
    float s = 0.f;
    for (int d = gdx; d < DD; d += 8) s = fmaf(hr[d], gw[d * En + e], s);
    part[tid] = s;
    __syncthreads();
    if (tid < En) {
        float l = 0.f;
        #pragma unroll
        for (int gg = 0; gg < 8; gg++) l += part[gg * 16 + tid];
        lg[tid] = l;
    }
    __syncthreads();
    if (tid == 0) {
        float mx = lg[0];
        for (int j = 1; j < En; j++) mx = fmaxf(mx, lg[j]);
        float prob[En]; float sum = 0.f;
        for (int j = 0; j < En; j++) { prob[j] = expf(lg[j] - mx); sum += prob[j]; }
        float inv = 1.f / sum;
        float sel[En];
        for (int j = 0; j < En; j++) { prob[j] *= inv; sel[j] = prob[j] + gbias[j]; }
        int i0 = 0; float b0 = sel[0];
        for (int j = 1; j < En; j++) if (sel[j] > b0) { b0 = sel[j]; i0 = j; }
        int i1 = -1; float b1 = -1e30f;
        for (int j = 0; j < En; j++) if (j != i0 && sel[j] > b1) { b1 = sel[j]; i1 = j; }
        float w0 = prob[i0], w1v = prob[i1], ws = w0 + w1v;
        g_idx[2*t]   = i0;      g_idx[2*t+1] = i1;
        g_wtk[2*t]   = w0 / ws; g_wtk[2*t+1] = w1v / ws;
        atomicAdd(&g_cnt[i0], 1);
        atomicAdd(&g_cnt[i1], 1);
    }
}

__global__ void scan_kernel() {
    int o = 0;
    for (int e = 0; e < En; e++) { g_off[e] = o; o += g_cnt[e]; g_cur[e] = 0; }
}

__global__ void scatter_kernel() {
    int p = blockIdx.x * 256 + threadIdx.x;
    if (p >= PAIRS) return;
    int e = g_idx[p];
    int pos = atomicAdd(&g_cur[e], 1);
    g_perm[g_off[e] + pos] = p;
}

__global__ void __launch_bounds__(256) moe_gemm_kernel(const float* __restrict__ W,
                                                       float* __restrict__ Cout,
                                                       int N, int K, int mode) {
    int e = blockIdx.z;
    int cnt = g_cnt[e];
    int by = blockIdx.y * 128;
    if (by >= cnt) return;
    int off = g_off[e];
    const float* B = W + (size_t)e * K * N;
    const int tid = threadIdx.x;
    const int tx = tid & 15, ty = tid >> 4;
    const int bx = blockIdx.x * 128;
    const int aRow = tid >> 1, aCol = (tid & 1) << 2;
    const int bRow = tid >> 5, bCol = (tid & 31) << 2;
    int gRow = by + aRow;
    bool av = gRow < cnt;
    const float* Aptr = 0;
    if (av) Aptr = (mode == 0) ? (g_h + (size_t)(g_perm[off + gRow] >> 1) * DD + aCol)
                               : ((const float*)g_gbuf + (size_t)(off + gRow) * Fn + aCol);
    __shared__ float As[8][128];
    __shared__ float Bs[8][128];
    float acc[8][8];
    #pragma unroll
    for (int i = 0; i < 8; i++)
        #pragma unroll
        for (int j = 0; j < 8; j++) acc[i][j] = 0.f;
    for (int k0 = 0; k0 < K; k0 += 8) {
        float4 a4 = av ? *(const float4*)(Aptr + k0) : make_float4(0.f,0.f,0.f,0.f);
        float4 b4 = *(const float4*)(B + (size_t)(k0 + bRow) * N + bx + bCol);
        As[aCol+0][aRow] = a4.x; As[aCol+1][aRow] = a4.y;
        As[aCol+2][aRow] = a4.z; As[aCol+3][aRow] = a4.w;
        *(float4*)&Bs[bRow][bCol] = b4;
        __syncthreads();
        #pragma unroll
        for (int kk = 0; kk < 8; kk++) MICROTILE_STEP(As, Bs, kk, acc);
        __syncthreads();
    }
    #pragma unroll
    for (int i = 0; i < 8; i++) {
        int r = by + ty*8 + i;
        if (r < cnt) {
            float* Cp;
            if (mode == 0) Cp = Cout + (size_t)(off + r) * N + bx + tx*8;
            else           Cp = g_y + (size_t)g_perm[off + r] * DD + bx + tx*8;
            *(float4*)Cp     = make_float4(acc[i][0],acc[i][1],acc[i][2],acc[i][3]);
            *(float4*)(Cp+4) = make_float4(acc[i][4],acc[i][5],acc[i][6],acc[i][7]);
        }
    }
}

__global__ void silu_mul_moe_kernel() {
    size_t i = (size_t)blockIdx.x * 256 + threadIdx.x;
    if (i >= (size_t)PAIRS * Fn) return;
    int ppos = (int)(i / Fn);
    int pair = g_perm[ppos];
    g_gbuf[i] = siluf(g_gbuf[i]) * g_ubuf[i] * g_wtk[pair];
}

__global__ void silu_mul_kernel(const float* __restrict__ a, const float* __restrict__ b,
                                float* __restrict__ o, size_t n) {
    size_t i = (size_t)blockIdx.x * 256 + threadIdx.x;
    if (i < n) o[i] = siluf(a[i]) * b[i];
}

__global__ void combine_kernel(float* __restrict__ out) {
    size_t i = (size_t)blockIdx.x * 256 + threadIdx.x;
    if (i >= (size_t)TT * DD) return;
    size_t t = i / DD, d = i % DD;
    out[i] = g_x2[i] + g_sharedY[i] + g_y[(2*t)*DD + d] + g_y[(2*t+1)*DD + d];
}

extern "C" void kernel_launch(void* const* d_in, const int* in_sizes, int n_in,
                              void* d_out, int out_size) {
    // sanity gate: if metadata order/count differs from assumption, launch nothing
    // -> harness reports "0 nodes" (distinct signal) instead of rel_err.
    if (n_in != 15) return;
    if (in_sizes[0] != 3*TT) return;          // positions
    if (in_sizes[5] != DD*NQKV) return;       // wqkv
    if (in_sizes[7] != DD*En) return;         // gate_w
    if (in_sizes[8] != En) return;            // gate_bias
    if (in_sizes[9] != (int)((size_t)En*DD*Fn)) return;  // w1

    const int*   positions = (const int*)d_in[0];
    const float* hidden    = (const float*)d_in[1];
    const float* w_norm1   = (const float*)d_in[3];
    const float* w_norm2   = (const float*)d_in[4];
    const float* wqkv      = (const float*)d_in[5];
    const float* wo        = (const float*)d_in[6];
    const float* gate_w    = (const float*)d_in[7];
    const float* gate_bias = (const float*)d_in[8];
    const float* w1        = (const float*)d_in[9];
    const float* w3        = (const float*)d_in[10];
    const float* w2        = (const float*)d_in[11];
    const float* ws1       = (const float*)d_in[12];
    const float* ws3       = (const float*)d_in[13];
    const float* ws2       = (const float*)d_in[14];
    float* out = (float*)d_out;

    float *p_xn, *p_qkv, *p_attn, *p_x2, *p_h, *p_s1, *p_s3, *p_sharedY, *p_gbuf, *p_ubuf;
    cudaGetSymbolAddress((void**)&p_xn, g_xn);
    cudaGetSymbolAddress((void**)&p_qkv, g_qkv);
    cudaGetSymbolAddress((void**)&p_attn, g_attn);
    cudaGetSymbolAddress((void**)&p_x2, g_x2);
    cudaGetSymbolAddress((void**)&p_h, g_h);
    cudaGetSymbolAddress((void**)&p_s1, g_s1);
    cudaGetSymbolAddress((void**)&p_s3, g_s3);
    cudaGetSymbolAddress((void**)&p_sharedY, g_sharedY);
    cudaGetSymbolAddress((void**)&p_gbuf, g_gbuf);
    cudaGetSymbolAddress((void**)&p_ubuf, g_ubuf);

    // attention block (fully re-derived front-end)
    rmsnorm_kernel<<<TT, 256>>>(hidden, w_norm1, p_xn);
    qkv_naive_kernel<<<dim3(NQKV/16, TT/16), dim3(16,16)>>>(p_xn, wqkv, p_qkv);
    ropek_kernel<<<dim3(TT, HKVn), 64>>>(p_qkv, positions);
    attn_fused_kernel<<<dim3(TT, HQn), 256>>>(p_qkv, positions, p_attn);
    sgemm_kernel<<<dim3(DD/128, TT/128), 256>>>(p_attn, wo, p_x2, hidden, DD, DD);

    // post-attn norm
    rmsnorm_kernel<<<TT, 256>>>(p_x2, w_norm2, p_h);

    // shared expert
    sgemm_kernel<<<dim3(FSn/128, TT/128), 256>>>(p_h, ws1, p_s1, (const float*)0, FSn, DD);
    sgemm_kernel<<<dim3(FSn/128, TT/128), 256>>>(p_h, ws3, p_s3, (const float*)0, FSn, DD);
    silu_mul_kernel<<<(int)(((size_t)TT*FSn + 255)/256), 256>>>(p_s1, p_s3, p_s1, (size_t)TT*FSn);
    sgemm_kernel<<<dim3(DD/128, TT/128), 256>>>(p_s1, ws2, p_sharedY, (const float*)0, DD, FSn);

    // MoE routing
    zero_cnt_kernel<<<1, 32>>>();
    gate_route_kernel<<<TT, 128>>>(gate_w, gate_bias);
    scan_kernel<<<1, 1>>>();
    scatter_kernel<<<(PAIRS + 255)/256, 256>>>();

    // grouped expert GEMMs
    moe_gemm_kernel<<<dim3(Fn/128, PAIRS/128, En), 256>>>(w1, p_gbuf, Fn, DD, 0);
    moe_gemm_kernel<<<dim3(Fn/128, PAIRS/128, En), 256>>>(w3, p_ubuf, Fn, DD, 0);
    silu_mul_moe_kernel<<<(int)(((size_t)PAIRS*Fn + 255)/256), 256>>>();
    moe_gemm_kernel<<<dim3(DD/128, PAIRS/128, En), 256>>>(w2, (float*)0, DD, Fn, 1);

    // final combine
    combine_kernel<<<(int)(((size_t)TT*DD + 255)/256), 256>>>(out);
}

// round 10
// speedup vs baseline: 1.1800x; 1.1800x over previous
#include <cuda_runtime.h>
#include <math.h>

#define TT   2048
#define DD   2048
#define HQn  16
#define HKVn 8
#define HDn  128
#define En   16
#define Fn   1024
#define FSn  2048
#define NQKV 4096
#define PAIRS (TT*2)

__device__ float g_xn[(size_t)TT*DD];
__device__ float g_qkv[(size_t)TT*NQKV];
__device__ float g_attn[(size_t)TT*DD];
__device__ float g_x2[(size_t)TT*DD];
__device__ float g_h[(size_t)TT*DD];
__device__ float g_s1[(size_t)TT*FSn];
__device__ float g_s3[(size_t)TT*FSn];
__device__ float g_sharedY[(size_t)TT*DD];
__device__ float g_gbuf[(size_t)PAIRS*Fn];
__device__ float g_ubuf[(size_t)PAIRS*Fn];
__device__ float g_y[(size_t)PAIRS*DD];
__device__ float g_k2[(size_t)TT*HKVn*HDn];   // roped K, layout [t][kvh][d]
__device__ int   g_idx[PAIRS];
__device__ float g_wtk[PAIRS];
__device__ int   g_cnt[En];
__device__ int   g_off[En];
__device__ int   g_cur[En];
__device__ int   g_perm[PAIRS];

__device__ __forceinline__ float siluf(float x) { return x / (1.f + expf(-x)); }

// fresh RoPE helper: pair index i (0..63), token t. Returns cos/sin.
__device__ __forceinline__ void rope_cs(const int* __restrict__ p32, int t, int i,
                                        float& c, float& s) {
    int sec = (i < 22) ? 0 : ((i < 44) ? 1 : 2);
    bool is64 = (p32[1] == 0);
    int lin = sec * TT + t;
    float pos = (float)(is64 ? p32[2*lin] : p32[lin]);
    float invf = (float)exp(-((double)i / 64.0) * log(500000.0));
    sincosf(pos * invf, &s, &c);
}

#define MICROTILE_STEP(As, Bs, kk, acc) do { \
    float4 a0 = *(const float4*)&As[kk][ty*8];   \
    float4 a1 = *(const float4*)&As[kk][ty*8+4]; \
    float4 b0 = *(const float4*)&Bs[kk][tx*8];   \
    float4 b1 = *(const float4*)&Bs[kk][tx*8+4]; \
    float ra[8] = {a0.x,a0.y,a0.z,a0.w,a1.x,a1.y,a1.z,a1.w}; \
    float rb[8] = {b0.x,b0.y,b0.z,b0.w,b1.x,b1.y,b1.z,b1.w}; \
    _Pragma("unroll") for (int i_ = 0; i_ < 8; i_++) \
      _Pragma("unroll") for (int j_ = 0; j_ < 8; j_++) \
        acc[i_][j_] = fmaf(ra[i_], rb[j_], acc[i_][j_]); \
} while (0)

__global__ void rmsnorm_kernel(const float* __restrict__ x, const float* __restrict__ w,
                               float* __restrict__ out) {
    int row = blockIdx.x;
    const float* xr = x + (size_t)row * DD;
    float* orow = out + (size_t)row * DD;
    float sum = 0.f;
    for (int i = threadIdx.x; i < DD; i += 256) { float v = xr[i]; sum = fmaf(v, v, sum); }
    __shared__ float red[8]; __shared__ float rinv;
    for (int o = 16; o > 0; o >>= 1) sum += __shfl_xor_sync(0xffffffffu, sum, o);
    if ((threadIdx.x & 31) == 0) red[threadIdx.x >> 5] = sum;
    __syncthreads();
    if (threadIdx.x == 0) {
        float s = 0.f;
        #pragma unroll
        for (int i = 0; i < 8; i++) s += red[i];
        rinv = rsqrtf(s / (float)DD + 1e-5f);
    }
    __syncthreads();
    float r = rinv;
    for (int i = threadIdx.x; i < DD; i += 256) orow[i] = xr[i] * r * w[i];
}

// ---------- out-of-place K rope: g_k2[t][kh][d] ----------
__global__ void ropek_kernel(const float* __restrict__ qkv, const int* __restrict__ p32) {
    int t = blockIdx.x, kh = blockIdx.y, i = threadIdx.x;   // i = pair 0..63
    const float* src = qkv + (size_t)t * NQKV + HQn*HDn + kh * HDn;
    float c, s;
    rope_cs(p32, t, i, c, s);
    float x1 = src[2*i], x2 = src[2*i+1];
    float* dst = g_k2 + ((size_t)t * HKVn + kh) * HDn;
    dst[2*i]   = x1 * c - x2 * s;
    dst[2*i+1] = x2 * c + x1 * s;
}

// ---------- fused brute-force attention: one block per (q, h) ----------
__global__ void __launch_bounds__(256) attn_fused_kernel(const float* __restrict__ qkv,
                                                         const int* __restrict__ p32,
                                                         float* __restrict__ attn) {
    int q = blockIdx.x, h = blockIdx.y;
    const int L = q + 1;
    const int kvh = h >> 1;
    const int tid = threadIdx.x;
    __shared__ float qs[HDn];
    __shared__ float sc[TT];
    __shared__ float red[8];
    __shared__ float bc;
    __shared__ float osum[256];
    const float scale = 0.08838834764831845f;   // 1/sqrt(128)

    // rope q inline, pre-scaled
    if (tid < 64) {
        const float* src = qkv + (size_t)q * NQKV + h * HDn;
        float c, s;
        rope_cs(p32, q, tid, c, s);
        float x1 = src[2*tid], x2 = src[2*tid+1];
        qs[2*tid]   = (x1 * c - x2 * s) * scale;
        qs[2*tid+1] = (x2 * c + x1 * s) * scale;
    }
    __syncthreads();

    // scores vs all k <= q
    for (int k = tid; k < L; k += 256) {
        const float* kp = g_k2 + ((size_t)k * HKVn + kvh) * HDn;
        float acc = 0.f;
        #pragma unroll 8
        for (int d = 0; d < HDn; d++) acc = fmaf(qs[d], kp[d], acc);
        sc[k] = acc;
    }
    __syncthreads();

    // softmax over sc[0..L-1]
    float mx = -INFINITY;
    for (int k = tid; k < L; k += 256) mx = fmaxf(mx, sc[k]);
    for (int o = 16; o > 0; o >>= 1) mx = fmaxf(mx, __shfl_xor_sync(0xffffffffu, mx, o));
    if ((tid & 31) == 0) red[tid >> 5] = mx;
    __syncthreads();
    if (tid == 0) {
        float m = red[0];
        #pragma unroll
        for (int i = 1; i < 8; i++) m = fmaxf(m, red[i]);
        bc = m;
    }
    __syncthreads();
    mx = bc;
    float sum = 0.f;
    for (int k = tid; k < L; k += 256) {
        float p = expf(sc[k] - mx);
        sc[k] = p;
        sum += p;
    }
    for (int o = 16; o > 0; o >>= 1) sum += __shfl_xor_sync(0xffffffffu, sum, o);
    if ((tid & 31) == 0) red[tid >> 5] = sum;
    __syncthreads();
    if (tid == 0) {
        float s = 0.f;
        #pragma unroll
        for (int i = 0; i < 8; i++) s += red[i];
        bc = 1.f / s;
    }
    __syncthreads();
    float inv = bc;

    // o[d] = sum_k p[k] * v[k][d]; 2 threads per d
    int d = tid & 127, half = tid >> 7;
    float o = 0.f;
    for (int k = half; k < L; k += 2)
        o = fmaf(sc[k], qkv[(size_t)k * NQKV + HQn*HDn + HKVn*HDn + kvh*HDn + d], o);
    osum[half * 128 + d] = o;
    __syncthreads();
    if (tid < 128)
        attn[(size_t)q * DD + h * HDn + tid] = (osum[tid] + osum[128 + tid]) * inv;
}

__global__ void __launch_bounds__(256) sgemm_kernel(
    const float* __restrict__ A, const float* __restrict__ B,
    float* __restrict__ C, const float* __restrict__ resid,
    int N, int K) {
    __shared__ float As[8][128];
    __shared__ float Bs[8][128];
    const int tid = threadIdx.x;
    const int tx = tid & 15, ty = tid >> 4;
    const int bx = blockIdx.x * 128, by = blockIdx.y * 128;
    const int aRow = tid >> 1, aCol = (tid & 1) << 2;
    const int bRow = tid >> 5, bCol = (tid & 31) << 2;
    const float* Aptr = A + (size_t)(by + aRow) * K + aCol;
    const float* Bptr = B + (size_t)bRow * N + bx + bCol;
    float acc[8][8];
    #pragma unroll
    for (int i = 0; i < 8; i++)
        #pragma unroll
        for (int j = 0; j < 8; j++) acc[i][j] = 0.f;
    for (int k0 = 0; k0 < K; k0 += 8) {
        float4 a4 = *(const float4*)(Aptr + k0);
        float4 b4 = *(const float4*)(Bptr + (size_t)k0 * N);
        As[aCol+0][aRow] = a4.x; As[aCol+1][aRow] = a4.y;
        As[aCol+2][aRow] = a4.z; As[aCol+3][aRow] = a4.w;
        *(float4*)&Bs[bRow][bCol] = b4;
        __syncthreads();
        #pragma unroll
        for (int kk = 0; kk < 8; kk++) MICROTILE_STEP(As, Bs, kk, acc);
        __syncthreads();
    }
    #pragma unroll
    for (int i = 0; i < 8; i++) {
        size_t r = (size_t)(by + ty*8 + i);
        float* Cp = C + r * N + bx + tx*8;
        float4 c0 = make_float4(acc[i][0],acc[i][1],acc[i][2],acc[i][3]);
        float4 c1 = make_float4(acc[i][4],acc[i][5],acc[i][6],acc[i][7]);
        if (resid) {
            const float* Rp = resid + r * N + bx + tx*8;
            float4 r0 = *(const float4*)Rp; float4 r1 = *(const float4*)(Rp+4);
            c0.x += r0.x; c0.y += r0.y; c0.z += r0.z; c0.w += r0.w;
            c1.x += r1.x; c1.y += r1.y; c1.z += r1.z; c1.w += r1.w;
        }
        *(float4*)Cp = c0; *(float4*)(Cp+4) = c1;
    }
}

__global__ void zero_cnt_kernel() { if (threadIdx.x < En) g_cnt[threadIdx.x] = 0; }

__global__ void gate_route_kernel(const float* __restrict__ gw, const float* __restrict__ gbias) {
    int t = blockIdx.x, tid = threadIdx.x;
    const float* hr = g_h + (size_t)t * DD;
    __shared__ float part[128];
    __shared__ float lg[En];
    int e = tid & 15, gdx = tid >> 4;
    float s = 0.f;
    for (int d = gdx; d < DD; d += 8) s = fmaf(hr[d], gw[d * En + e], s);
    part[tid] = s;
    __syncthreads();
    if (tid < En) {
        float l = 0.f;
        #pragma unroll
        for (int gg = 0; gg < 8; gg++) l += part[gg * 16 + tid];
        lg[tid] = l;
    }
    __syncthreads();
    if (tid == 0) {
        float mx = lg[0];
        for (int j = 1; j < En; j++) mx = fmaxf(mx, lg[j]);
        float prob[En]; float sum = 0.f;
        for (int j = 0; j < En; j++) { prob[j] = expf(lg[j] - mx); sum += prob[j]; }
        float inv = 1.f / sum;
        float sel[En];
        for (int j = 0; j < En; j++) { prob[j] *= inv; sel[j] = prob[j] + gbias[j]; }
        int i0 = 0; float b0 = sel[0];
        for (int j = 1; j < En; j++) if (sel[j] > b0) { b0 = sel[j]; i0 = j; }
        int i1 = -1; float b1 = -1e30f;
        for (int j = 0; j < En; j++) if (j != i0 && sel[j] > b1) { b1 = sel[j]; i1 = j; }
        float w0 = prob[i0], w1v = prob[i1], ws = w0 + w1v;
        g_idx[2*t]   = i0;      g_idx[2*t+1] = i1;
        g_wtk[2*t]   = w0 / ws; g_wtk[2*t+1] = w1v / ws;
        atomicAdd(&g_cnt[i0], 1);
        atomicAdd(&g_cnt[i1], 1);
    }
}

__global__ void scan_kernel() {
    int o = 0;
    for (int e = 0; e < En; e++) { g_off[e] = o; o += g_cnt[e]; g_cur[e] = 0; }
}

__global__ void scatter_kernel() {
    int p = blockIdx.x * 256 + threadIdx.x;
    if (p >= PAIRS) return;
    int e = g_idx[p];
    int pos = atomicAdd(&g_cur[e], 1);
    g_perm[g_off[e] + pos] = p;
}

__global__ void __launch_bounds__(256) moe_gemm_kernel(const float* __restrict__ W,
                                                       float* __restrict__ Cout,
                                                       int N, int K, int mode) {
    int e = blockIdx.z;
    int cnt = g_cnt[e];
    int by = blockIdx.y * 128;
    if (by >= cnt) return;
    int off = g_off[e];
    const float* B = W + (size_t)e * K * N;
    const int tid = threadIdx.x;
    const int tx = tid & 15, ty = tid >> 4;
    const int bx = blockIdx.x * 128;
    const int aRow = tid >> 1, aCol = (tid & 1) << 2;
    const int bRow = tid >> 5, bCol = (tid & 31) << 2;
    int gRow = by + aRow;
    bool av = gRow < cnt;
    const float* Aptr = 0;
    if (av) Aptr = (mode == 0) ? (g_h + (size_t)(g_perm[off + gRow] >> 1) * DD + aCol)
                               : ((const float*)g_gbuf + (size_t)(off + gRow) * Fn + aCol);
    __shared__ float As[8][128];
    __shared__ float Bs[8][128];
    float acc[8][8];
    #pragma unroll
    for (int i = 0; i < 8; i++)
        #pragma unroll
        for (int j = 0; j < 8; j++) acc[i][j] = 0.f;
    for (int k0 = 0; k0 < K; k0 += 8) {
        float4 a4 = av ? *(const float4*)(Aptr + k0) : make_float4(0.f,0.f,0.f,0.f);
        float4 b4 = *(const float4*)(B + (size_t)(k0 + bRow) * N + bx + bCol);
        As[aCol+0][aRow] = a4.x; As[aCol+1][aRow] = a4.y;
        As[aCol+2][aRow] = a4.z; As[aCol+3][aRow] = a4.w;
        *(float4*)&Bs[bRow][bCol] = b4;
        __syncthreads();
        #pragma unroll
        for (int kk = 0; kk < 8; kk++) MICROTILE_STEP(As, Bs, kk, acc);
        __syncthreads();
    }
    #pragma unroll
    for (int i = 0; i < 8; i++) {
        int r = by + ty*8 + i;
        if (r < cnt) {
            float* Cp;
            if (mode == 0) Cp = Cout + (size_t)(off + r) * N + bx + tx*8;
            else           Cp = g_y + (size_t)g_perm[off + r] * DD + bx + tx*8;
            *(float4*)Cp     = make_float4(acc[i][0],acc[i][1],acc[i][2],acc[i][3]);
            *(float4*)(Cp+4) = make_float4(acc[i][4],acc[i][5],acc[i][6],acc[i][7]);
        }
    }
}

__global__ void silu_mul_moe_kernel() {
    size_t i = (size_t)blockIdx.x * 256 + threadIdx.x;
    if (i >= (size_t)PAIRS * Fn) return;
    int ppos = (int)(i / Fn);
    int pair = g_perm[ppos];
    g_gbuf[i] = siluf(g_gbuf[i]) * g_ubuf[i] * g_wtk[pair];
}

__global__ void silu_mul_kernel(const float* __restrict__ a, const float* __restrict__ b,
                                float* __restrict__ o, size_t n) {
    size_t i = (size_t)blockIdx.x * 256 + threadIdx.x;
    if (i < n) o[i] = siluf(a[i]) * b[i];
}

__global__ void combine_kernel(float* __restrict__ out) {
    size_t i = (size_t)blockIdx.x * 256 + threadIdx.x;
    if (i >= (size_t)TT * DD) return;
    size_t t = i / DD, d = i % DD;
    out[i] = g_x2[i] + g_sharedY[i] + g_y[(2*t)*DD + d] + g_y[(2*t+1)*DD + d];
}

extern "C" void kernel_launch(void* const* d_in, const int* in_sizes, int n_in,
                              void* d_out, int out_size) {
    if (n_in != 15) return;
    if (in_sizes[0] != 3*TT) return;          // positions
    if (in_sizes[5] != DD*NQKV) return;       // wqkv
    if (in_sizes[7] != DD*En) return;         // gate_w
    if (in_sizes[8] != En) return;            // gate_bias
    if (in_sizes[9] != (int)((size_t)En*DD*Fn)) return;  // w1

    const int*   positions = (const int*)d_in[0];
    const float* hidden    = (const float*)d_in[1];
    const float* w_norm1   = (const float*)d_in[3];
    const float* w_norm2   = (const float*)d_in[4];
    const float* wqkv      = (const float*)d_in[5];
    const float* wo        = (const float*)d_in[6];
    const float* gate_w    = (const float*)d_in[7];
    const float* gate_bias = (const float*)d_in[8];
    const float* w1        = (const float*)d_in[9];
    const float* w3        = (const float*)d_in[10];
    const float* w2        = (const float*)d_in[11];
    const float* ws1       = (const float*)d_in[12];
    const float* ws3       = (const float*)d_in[13];
    const float* ws2       = (const float*)d_in[14];
    float* out = (float*)d_out;

    float *p_xn, *p_qkv, *p_attn, *p_x2, *p_h, *p_s1, *p_s3, *p_sharedY, *p_gbuf, *p_ubuf;
    cudaGetSymbolAddress((void**)&p_xn, g_xn);
    cudaGetSymbolAddress((void**)&p_qkv, g_qkv);
    cudaGetSymbolAddress((void**)&p_attn, g_attn);
    cudaGetSymbolAddress((void**)&p_x2, g_x2);
    cudaGetSymbolAddress((void**)&p_h, g_h);
    cudaGetSymbolAddress((void**)&p_s1, g_s1);
    cudaGetSymbolAddress((void**)&p_s3, g_s3);
    cudaGetSymbolAddress((void**)&p_sharedY, g_sharedY);
    cudaGetSymbolAddress((void**)&p_gbuf, g_gbuf);
    cudaGetSymbolAddress((void**)&p_ubuf, g_ubuf);

    // attention block — QKV now via the fast 128x128 sgemm (the bisect experiment)
    rmsnorm_kernel<<<TT, 256>>>(hidden, w_norm1, p_xn);
    sgemm_kernel<<<dim3(NQKV/128, TT/128), 256>>>(p_xn, wqkv, p_qkv, (const float*)0, NQKV, DD);
    ropek_kernel<<<dim3(TT, HKVn), 64>>>(p_qkv, positions);
    attn_fused_kernel<<<dim3(TT, HQn), 256>>>(p_qkv, positions, p_attn);
    sgemm_kernel<<<dim3(DD/128, TT/128), 256>>>(p_attn, wo, p_x2, hidden, DD, DD);

    // post-attn norm
    rmsnorm_kernel<<<TT, 256>>>(p_x2, w_norm2, p_h);

    // shared expert
    sgemm_kernel<<<dim3(FSn/128, TT/128), 256>>>(p_h, ws1, p_s1, (const float*)0, FSn, DD);
    sgemm_kernel<<<dim3(FSn/128, TT/128), 256>>>(p_h, ws3, p_s3, (const float*)0, FSn, DD);
    silu_mul_kernel<<<(int)(((size_t)TT*FSn + 255)/256), 256>>>(p_s1, p_s3, p_s1, (size_t)TT*FSn);
    sgemm_kernel<<<dim3(DD/128, TT/128), 256>>>(p_s1, ws2, p_sharedY, (const float*)0, DD, FSn);

    // MoE routing
    zero_cnt_kernel<<<1, 32>>>();
    gate_route_kernel<<<TT, 128>>>(gate_w, gate_bias);
    scan_kernel<<<1, 1>>>();
    scatter_kernel<<<(PAIRS + 255)/256, 256>>>();

    // grouped expert GEMMs
    moe_gemm_kernel<<<dim3(Fn/128, PAIRS/128, En), 256>>>(w1, p_gbuf, Fn, DD, 0);
    moe_gemm_kernel<<<dim3(Fn/128, PAIRS/128, En), 256>>>(w3, p_ubuf, Fn, DD, 0);
    silu_mul_moe_kernel<<<(int)(((size_t)PAIRS*Fn + 255)/256), 256>>>();
    moe_gemm_kernel<<<dim3(DD/128, PAIRS/128, En), 256>>>(w2, (float*)0, DD, Fn, 1);

    // final combine
    combine_kernel<<<(int)(((size_t)TT*DD + 255)/256), 256>>>(out);
}

// round 11
// speedup vs baseline: 5.5679x; 4.7185x over previous
#include <cuda_runtime.h>
#include <math.h>
#include <stdint.h>

#define TT   2048
#define DD   2048
#define HQn  16
#define HKVn 8
#define HDn  128
#define En   16
#define Fn   1024
#define FSn  2048
#define NQKV 4096
#define PAIRS (TT*2)

__device__ float g_xn[(size_t)TT*DD];
__device__ float g_qkv[(size_t)TT*NQKV];
__device__ float g_attn[(size_t)TT*DD];
__device__ float g_x2[(size_t)TT*DD];
__device__ float g_h[(size_t)TT*DD];
__device__ float g_s1[(size_t)TT*FSn];
__device__ float g_s3[(size_t)TT*FSn];
__device__ float g_sharedY[(size_t)TT*DD];
__device__ float g_gbuf[(size_t)PAIRS*Fn];
__device__ float g_ubuf[(size_t)PAIRS*Fn];
__device__ float g_y[(size_t)PAIRS*DD];
__device__ float g_k2[(size_t)TT*HKVn*HDn];   // roped K, layout [t][kvh][d]
__device__ int   g_idx[PAIRS];
__device__ float g_wtk[PAIRS];
__device__ int   g_cnt[En];
__device__ int   g_off[En];
__device__ int   g_cur[En];
__device__ int   g_perm[PAIRS];

__device__ __forceinline__ float siluf(float x) { return x / (1.f + expf(-x)); }

// RoPE helper: pair index i (0..63), token t.
__device__ __forceinline__ void rope_cs(const int* __restrict__ p32, int t, int i,
                                        float& c, float& s) {
    int sec = (i < 22) ? 0 : ((i < 44) ? 1 : 2);
    bool is64 = (p32[1] == 0);
    int lin = sec * TT + t;
    float pos = (float)(is64 ? p32[2*lin] : p32[lin]);
    float invf = (float)exp(-((double)i / 64.0) * log(500000.0));
    sincosf(pos * invf, &s, &c);
}

__device__ __forceinline__ float to_tf32(float x) {
    uint32_t u;
    asm("cvt.rna.tf32.f32 %0, %1;" : "=r"(u) : "f"(x));
    return __uint_as_float(u);
}

#define MICROTILE_STEP(As, Bs, kk, acc) do { \
    float4 a0 = *(const float4*)&As[kk][ty*8];   \
    float4 a1 = *(const float4*)&As[kk][ty*8+4]; \
    float4 b0 = *(const float4*)&Bs[kk][tx*8];   \
    float4 b1 = *(const float4*)&Bs[kk][tx*8+4]; \
    float ra[8] = {a0.x,a0.y,a0.z,a0.w,a1.x,a1.y,a1.z,a1.w}; \
    float rb[8] = {b0.x,b0.y,b0.z,b0.w,b1.x,b1.y,b1.z,b1.w}; \
    _Pragma("unroll") for (int i_ = 0; i_ < 8; i_++) \
      _Pragma("unroll") for (int j_ = 0; j_ < 8; j_++) \
        acc[i_][j_] = fmaf(ra[i_], rb[j_], acc[i_][j_]); \
} while (0)

__global__ void rmsnorm_kernel(const float* __restrict__ x, const float* __restrict__ w,
                               float* __restrict__ out) {
    int row = blockIdx.x;
    const float* xr = x + (size_t)row * DD;
    float* orow = out + (size_t)row * DD;
    float sum = 0.f;
    for (int i = threadIdx.x; i < DD; i += 256) { float v = xr[i]; sum = fmaf(v, v, sum); }
    __shared__ float red[8]; __shared__ float rinv;
    for (int o = 16; o > 0; o >>= 1) sum += __shfl_xor_sync(0xffffffffu, sum, o);
    if ((threadIdx.x & 31) == 0) red[threadIdx.x >> 5] = sum;
    __syncthreads();
    if (threadIdx.x == 0) {
        float s = 0.f;
        #pragma unroll
        for (int i = 0; i < 8; i++) s += red[i];
        rinv = rsqrtf(s / (float)DD + 1e-5f);
    }
    __syncthreads();
    float r = rinv;
    for (int i = threadIdx.x; i < DD; i += 256) orow[i] = xr[i] * r * w[i];
}

// ---------- out-of-place K rope: g_k2[t][kh][d] (PROVEN) ----------
__global__ void ropek_kernel(const float* __restrict__ qkv, const int* __restrict__ p32) {
    int t = blockIdx.x, kh = blockIdx.y, i = threadIdx.x;
    const float* src = qkv + (size_t)t * NQKV + HQn*HDn + kh * HDn;
    float c, s;
    rope_cs(p32, t, i, c, s);
    float x1 = src[2*i], x2 = src[2*i+1];
    float* dst = g_k2 + ((size_t)t * HKVn + kh) * HDn;
    dst[2*i]   = x1 * c - x2 * s;
    dst[2*i+1] = x2 * c + x1 * s;
}

// ---------- fp32 SGEMM (QKV + wo; stays fp32 for routing stability) ----------
__global__ void __launch_bounds__(256) sgemm_kernel(
    const float* __restrict__ A, const float* __restrict__ B,
    float* __restrict__ C, const float* __restrict__ resid,
    int N, int K) {
    __shared__ float As[8][128];
    __shared__ float Bs[8][128];
    const int tid = threadIdx.x;
    const int tx = tid & 15, ty = tid >> 4;
    const int bx = blockIdx.x * 128, by = blockIdx.y * 128;
    const int aRow = tid >> 1, aCol = (tid & 1) << 2;
    const int bRow = tid >> 5, bCol = (tid & 31) << 2;
    const float* Aptr = A + (size_t)(by + aRow) * K + aCol;
    const float* Bptr = B + (size_t)bRow * N + bx + bCol;
    float acc[8][8];
    #pragma unroll
    for (int i = 0; i < 8; i++)
        #pragma unroll
        for (int j = 0; j < 8; j++) acc[i][j] = 0.f;
    for (int k0 = 0; k0 < K; k0 += 8) {
        float4 a4 = *(const float4*)(Aptr + k0);
        float4 b4 = *(const float4*)(Bptr + (size_t)k0 * N);
        As[aCol+0][aRow] = a4.x; As[aCol+1][aRow] = a4.y;
        As[aCol+2][aRow] = a4.z; As[aCol+3][aRow] = a4.w;
        *(float4*)&Bs[bRow][bCol] = b4;
        __syncthreads();
        #pragma unroll
        for (int kk = 0; kk < 8; kk++) MICROTILE_STEP(As, Bs, kk, acc);
        __syncthreads();
    }
    #pragma unroll
    for (int i = 0; i < 8; i++) {
        size_t r = (size_t)(by + ty*8 + i);
        float* Cp = C + r * N + bx + tx*8;
        float4 c0 = make_float4(acc[i][0],acc[i][1],acc[i][2],acc[i][3]);
        float4 c1 = make_float4(acc[i][4],acc[i][5],acc[i][6],acc[i][7]);
        if (resid) {
            const float* Rp = resid + r * N + bx + tx*8;
            float4 r0 = *(const float4*)Rp; float4 r1 = *(const float4*)(Rp+4);
            c0.x += r0.x; c0.y += r0.y; c0.z += r0.z; c0.w += r0.w;
            c1.x += r1.x; c1.y += r1.y; c1.z += r1.z; c1.w += r1.w;
        }
        *(float4*)Cp = c0; *(float4*)(Cp+4) = c1;
    }
}

// ---------- tiled flash attention: 64 q x 64 k tiles, K from g_k2, Q roped inline ----------
#define FA_SMEM_BYTES ((128*68*2 + 64*132 + 64*66 + 192) * 4)
__global__ void __launch_bounds__(256) flash_kernel(const float* __restrict__ qkv,
                                                    const int* __restrict__ p32,
                                                    float* __restrict__ attn) {
    extern __shared__ float sm[];
    float* Qt   = sm;                 // [hd=128][q 64+4] transposed, roped+scaled
    float* Kt   = Qt + 128*68;        // [hd=128][k 64+4] transposed (from g_k2)
    float* Vs   = Kt + 128*68;        // [k=64][hd 128+4]
    float* Ss   = Vs + 64*132;        // [q=64][k 64+2]
    float* mrow = Ss + 64*66;
    float* lrow = mrow + 64;
    float* arow = lrow + 64;
    const int qt = blockIdx.x, h = blockIdx.y;
    const int qbase = qt * 64;
    const int tid = threadIdx.x;
    const int tx = tid & 15, ty = tid >> 4;
    const float scale = 0.08838834764831845f;   // 1/sqrt(128)
    const int kvh = h >> 1;
    const int vcol = HQn*HDn + HKVn*HDn + kvh * HDn;

    // load + rope + scale Q tile (transposed)
    for (int idx = tid; idx < 64*32; idx += 256) {
        int r = idx >> 5, c4 = (idx & 31) << 2;
        int t = qbase + r;
        float4 q4 = *(const float4*)&qkv[(size_t)t * NQKV + h*HDn + c4];
        float c0, s0, c1, s1;
        rope_cs(p32, t, c4/2,     c0, s0);
        rope_cs(p32, t, c4/2 + 1, c1, s1);
        Qt[(c4+0)*68 + r] = (q4.x * c0 - q4.y * s0) * scale;
        Qt[(c4+1)*68 + r] = (q4.y * c0 + q4.x * s0) * scale;
        Qt[(c4+2)*68 + r] = (q4.z * c1 - q4.w * s1) * scale;
        Qt[(c4+3)*68 + r] = (q4.w * c1 + q4.z * s1) * scale;
    }
    if (tid < 64) { mrow[tid] = -INFINITY; lrow[tid] = 0.f; }
    float o[4][8];
    #pragma unroll
    for (int i = 0; i < 4; i++)
        #pragma unroll
        for (int j = 0; j < 8; j++) o[i][j] = 0.f;

    for (int kt = 0; kt <= qt; kt++) {
        const int kbase = kt * 64;
        __syncthreads();
        for (int idx = tid; idx < 64*32; idx += 256) {
            int r = idx >> 5, c4 = (idx & 31) << 2;
            float4 k4 = *(const float4*)&g_k2[((size_t)(kbase + r) * HKVn + kvh) * HDn + c4];
            Kt[(c4+0)*68 + r] = k4.x;
            Kt[(c4+1)*68 + r] = k4.y;
            Kt[(c4+2)*68 + r] = k4.z;
            Kt[(c4+3)*68 + r] = k4.w;
            float4 v4 = *(const float4*)&qkv[(size_t)(kbase + r) * NQKV + vcol + c4];
            *(float4*)&Vs[r*132 + c4] = v4;
        }
        __syncthreads();
        float sacc[4][4];
        #pragma unroll
        for (int i = 0; i < 4; i++)
            #pragma unroll
            for (int c = 0; c < 4; c++) sacc[i][c] = 0.f;
        #pragma unroll 8
        for (int kk = 0; kk < 128; kk++) {
            float4 qa = *(const float4*)&Qt[kk*68 + ty*4];
            float4 kb = *(const float4*)&Kt[kk*68 + tx*4];
            float ra[4] = {qa.x,qa.y,qa.z,qa.w};
            float rb[4] = {kb.x,kb.y,kb.z,kb.w};
            #pragma unroll
            for (int i = 0; i < 4; i++)
                #pragma unroll
                for (int c = 0; c < 4; c++)
                    sacc[i][c] = fmaf(ra[i], rb[c], sacc[i][c]);
        }
        const bool diag = (kt == qt);
        #pragma unroll
        for (int i = 0; i < 4; i++) {
            int r = ty*4 + i;
            #pragma unroll
            for (int c = 0; c < 4; c++) {
                int cc = tx*4 + c;
                float v = sacc[i][c];
                if (diag && cc > r) v = -1e30f;
                Ss[r*66 + cc] = v;
            }
        }
        __syncthreads();
        {
            int r = tid >> 2, q = tid & 3;
            float m0 = mrow[r];
            float mx = m0;
            for (int j = q; j < 64; j += 4) mx = fmaxf(mx, Ss[r*66 + j]);
            mx = fmaxf(mx, __shfl_xor_sync(0xffffffffu, mx, 1));
            mx = fmaxf(mx, __shfl_xor_sync(0xffffffffu, mx, 2));
            float sum = 0.f;
            for (int j = q; j < 64; j += 4) {
                float p = expf(Ss[r*66 + j] - mx);
                Ss[r*66 + j] = p;
                sum += p;
            }
            sum += __shfl_xor_sync(0xffffffffu, sum, 1);
            sum += __shfl_xor_sync(0xffffffffu, sum, 2);
            if (q == 0) {
                float al = expf(m0 - mx);
                lrow[r] = lrow[r] * al + sum;
                mrow[r] = mx;
                arow[r] = al;
            }
        }
        __syncthreads();
        float av[4];
        #pragma unroll
        for (int i = 0; i < 4; i++) av[i] = arow[ty*4 + i];
        #pragma unroll
        for (int i = 0; i < 4; i++)
            #pragma unroll
            for (int j = 0; j < 8; j++) o[i][j] *= av[i];
        #pragma unroll 4
        for (int jk = 0; jk < 64; jk++) {
            float p0 = Ss[(ty*4+0)*66 + jk];
            float p1 = Ss[(ty*4+1)*66 + jk];
            float p2 = Ss[(ty*4+2)*66 + jk];
            float p3 = Ss[(ty*4+3)*66 + jk];
            float4 v0 = *(const float4*)&Vs[jk*132 + tx*8];
            float4 v1 = *(const float4*)&Vs[jk*132 + tx*8 + 4];
            float rv[8] = {v0.x,v0.y,v0.z,v0.w,v1.x,v1.y,v1.z,v1.w};
            #pragma unroll
            for (int j = 0; j < 8; j++) {
                o[0][j] = fmaf(p0, rv[j], o[0][j]);
                o[1][j] = fmaf(p1, rv[j], o[1][j]);
                o[2][j] = fmaf(p2, rv[j], o[2][j]);
                o[3][j] = fmaf(p3, rv[j], o[3][j]);
            }
        }
    }
    #pragma unroll
    for (int i = 0; i < 4; i++) {
        int r = ty*4 + i;
        float inv = 1.f / lrow[r];
        float* dst = attn + (size_t)(qbase + r) * DD + h*HDn + tx*8;
        *(float4*)dst     = make_float4(o[i][0]*inv, o[i][1]*inv, o[i][2]*inv, o[i][3]*inv);
        *(float4*)(dst+4) = make_float4(o[i][4]*inv, o[i][5]*inv, o[i][6]*inv, o[i][7]*inv);
    }
}

// ---------- tf32 tensor-core GEMM (post-routing GEMMs) ----------
// mode 0: dense  C[r*N]        = A[r*K] @ B
// mode 1: moe-up C[(off+r)*N]  = g_h[perm[off+r]>>1] @ (B + e*K*N)
// mode 2: moe-dn g_y[perm*N]   = g_gbuf[(off+r)*K]   @ (B + e*K*N)
__global__ void __launch_bounds__(256) tf32_gemm_kernel(
    const float* __restrict__ A, const float* __restrict__ B, float* __restrict__ C,
    int N, int K, int mode) {
    __shared__ float As[128][36];
    __shared__ float Bs[32][136];
    const int tid = threadIdx.x;
    const int bx = blockIdx.x * 128, by = blockIdx.y * 128;
    int cnt = 1 << 30, off = 0;
    const float* Bp = B;
    if (mode != 0) {
        int e = blockIdx.z;
        cnt = g_cnt[e]; off = g_off[e];
        if (by >= cnt) return;
        Bp = B + (size_t)e * K * N;
    }
    const int arow = tid >> 1, acol = (tid & 1) * 16;
    const int gRow = by + arow;
    const bool av = gRow < cnt;
    const float* aptr = 0;
    if (mode == 0)           aptr = A + (size_t)gRow * K;
    else if (av && mode == 1) aptr = g_h + (size_t)(g_perm[off + gRow] >> 1) * DD;
    else if (av)             aptr = g_gbuf + (size_t)(off + gRow) * K;
    const int brow = tid >> 3, bcol = (tid & 7) * 16;

    float acc[4][4][4];
    #pragma unroll
    for (int mt = 0; mt < 4; mt++)
        #pragma unroll
        for (int nt = 0; nt < 4; nt++)
            #pragma unroll
            for (int z = 0; z < 4; z++) acc[mt][nt][z] = 0.f;

    const int warp = tid >> 5, lane = tid & 31;
    const int wm = (warp & 1) * 64, wn = (warp >> 1) * 32;
    const int g = lane >> 2, tg = lane & 3;

    for (int k0 = 0; k0 < K; k0 += 32) {
        #pragma unroll
        for (int j = 0; j < 4; j++) {
            float4 a4 = av ? *(const float4*)(aptr + k0 + acol + 4*j)
                           : make_float4(0.f,0.f,0.f,0.f);
            As[arow][acol+4*j+0] = to_tf32(a4.x);
            As[arow][acol+4*j+1] = to_tf32(a4.y);
            As[arow][acol+4*j+2] = to_tf32(a4.z);
            As[arow][acol+4*j+3] = to_tf32(a4.w);
            float4 b4 = *(const float4*)(Bp + (size_t)(k0 + brow) * N + bx + bcol + 4*j);
            Bs[brow][bcol+4*j+0] = to_tf32(b4.x);
            Bs[brow][bcol+4*j+1] = to_tf32(b4.y);
            Bs[brow][bcol+4*j+2] = to_tf32(b4.z);
            Bs[brow][bcol+4*j+3] = to_tf32(b4.w);
        }
        __syncthreads();
        #pragma unroll
        for (int kk = 0; kk < 32; kk += 8) {
            float af[4][4]; float bf[4][2];
            #pragma unroll
            for (int mt = 0; mt < 4; mt++) {
                int r0 = wm + mt*16 + g;
                af[mt][0] = As[r0][kk+tg];
                af[mt][1] = As[r0+8][kk+tg];
                af[mt][2] = As[r0][kk+tg+4];
                af[mt][3] = As[r0+8][kk+tg+4];
            }
            #pragma unroll
            for (int nt = 0; nt < 4; nt++) {
                int cc = wn + nt*8 + g;
                bf[nt][0] = Bs[kk+tg][cc];
                bf[nt][1] = Bs[kk+tg+4][cc];
            }
            #pragma unroll
            for (int mt = 0; mt < 4; mt++)
                #pragma unroll
                for (int nt = 0; nt < 4; nt++)
                    asm volatile(
                        "mma.sync.aligned.m16n8k8.row.col.f32.tf32.tf32.f32 "
                        "{%0,%1,%2,%3}, {%4,%5,%6,%7}, {%8,%9}, {%0,%1,%2,%3};"
                        : "+f"(acc[mt][nt][0]), "+f"(acc[mt][nt][1]),
                          "+f"(acc[mt][nt][2]), "+f"(acc[mt][nt][3])
                        : "r"(__float_as_uint(af[mt][0])), "r"(__float_as_uint(af[mt][1])),
                          "r"(__float_as_uint(af[mt][2])), "r"(__float_as_uint(af[mt][3])),
                          "r"(__float_as_uint(bf[nt][0])), "r"(__float_as_uint(bf[nt][1])));
        }
        __syncthreads();
    }
    #pragma unroll
    for (int mt = 0; mt < 4; mt++) {
        #pragma unroll
        for (int half = 0; half < 2; half++) {
            int r = by + wm + mt*16 + g + half*8;
            if (r >= cnt) continue;
            float* crow;
            if (mode == 0)      crow = C + (size_t)r * N;
            else if (mode == 1) crow = C + (size_t)(off + r) * N;
            else                crow = g_y + (size_t)g_perm[off + r] * N;
            #pragma unroll
            for (int nt = 0; nt < 4; nt++) {
                int cc = bx + wn + nt*8 + 2*tg;
                crow[cc]   = acc[mt][nt][half*2+0];
                crow[cc+1] = acc[mt][nt][half*2+1];
            }
        }
    }
}

__global__ void zero_cnt_kernel() { if (threadIdx.x < En) g_cnt[threadIdx.x] = 0; }

__global__ void gate_route_kernel(const float* __restrict__ gw, const float* __restrict__ gbias) {
    int t = blockIdx.x, tid = threadIdx.x;
    const float* hr = g_h + (size_t)t * DD;
    __shared__ float part[128];
    __shared__ float lg[En];
    int e = tid & 15, gdx = tid >> 4;
    float s = 0.f;
    for (int d = gdx; d < DD; d += 8) s = fmaf(hr[d], gw[d * En + e], s);
    part[tid] = s;
    __syncthreads();
    if (tid < En) {
        float l = 0.f;
        #pragma unroll
        for (int gg = 0; gg < 8; gg++) l += part[gg * 16 + tid];
        lg[tid] = l;
    }
    __syncthreads();
    if (tid == 0) {
        float mx = lg[0];
        for (int j = 1; j < En; j++) mx = fmaxf(mx, lg[j]);
        float prob[En]; float sum = 0.f;
        for (int j = 0; j < En; j++) { prob[j] = expf(lg[j] - mx); sum += prob[j]; }
        float inv = 1.f / sum;
        float sel[En];
        for (int j = 0; j < En; j++) { prob[j] *= inv; sel[j] = prob[j] + gbias[j]; }
        int i0 = 0; float b0 = sel[0];
        for (int j = 1; j < En; j++) if (sel[j] > b0) { b0 = sel[j]; i0 = j; }
        int i1 = -1; float b1 = -1e30f;
        for (int j = 0; j < En; j++) if (j != i0 && sel[j] > b1) { b1 = sel[j]; i1 = j; }
        float w0 = prob[i0], w1v = prob[i1], ws = w0 + w1v;
        g_idx[2*t]   = i0;      g_idx[2*t+1] = i1;
        g_wtk[2*t]   = w0 / ws; g_wtk[2*t+1] = w1v / ws;
        atomicAdd(&g_cnt[i0], 1);
        atomicAdd(&g_cnt[i1], 1);
    }
}

__global__ void scan_kernel() {
    int o = 0;
    for (int e = 0; e < En; e++) { g_off[e] = o; o += g_cnt[e]; g_cur[e] = 0; }
}

__global__ void scatter_kernel() {
    int p = blockIdx.x * 256 + threadIdx.x;
    if (p >= PAIRS) return;
    int e = g_idx[p];
    int pos = atomicAdd(&g_cur[e], 1);
    g_perm[g_off[e] + pos] = p;
}

__global__ void silu_mul_moe_kernel() {
    size_t i = (size_t)blockIdx.x * 256 + threadIdx.x;
    if (i >= (size_t)PAIRS * Fn) return;
    int ppos = (int)(i / Fn);
    int pair = g_perm[ppos];
    g_gbuf[i] = siluf(g_gbuf[i]) * g_ubuf[i] * g_wtk[pair];
}

__global__ void silu_mul_kernel(const float* __restrict__ a, const float* __restrict__ b,
                                float* __restrict__ o, size_t n) {
    size_t i = (size_t)blockIdx.x * 256 + threadIdx.x;
    if (i < n) o[i] = siluf(a[i]) * b[i];
}

__global__ void combine_kernel(float* __restrict__ out) {
    size_t i = (size_t)blockIdx.x * 256 + threadIdx.x;
    if (i >= (size_t)TT * DD) return;
    size_t t = i / DD, d = i % DD;
    out[i] = g_x2[i] + g_sharedY[i] + g_y[(2*t)*DD + d] + g_y[(2*t+1)*DD + d];
}

extern "C" void kernel_launch(void* const* d_in, const int* in_sizes, int n_in,
                              void* d_out, int out_size) {
    if (n_in != 15) return;
    if (in_sizes[0] != 3*TT) return;
    if (in_sizes[5] != DD*NQKV) return;
    if (in_sizes[7] != DD*En) return;
    if (in_sizes[8] != En) return;
    if (in_sizes[9] != (int)((size_t)En*DD*Fn)) return;

    const int*   positions = (const int*)d_in[0];
    const float* hidden    = (const float*)d_in[1];
    const float* w_norm1   = (const float*)d_in[3];
    const float* w_norm2   = (const float*)d_in[4];
    const float* wqkv      = (const float*)d_in[5];
    const float* wo        = (const float*)d_in[6];
    const float* gate_w    = (const float*)d_in[7];
    const float* gate_bias = (const float*)d_in[8];
    const float* w1        = (const float*)d_in[9];
    const float* w3        = (const float*)d_in[10];
    const float* w2        = (const float*)d_in[11];
    const float* ws1       = (const float*)d_in[12];
    const float* ws3       = (const float*)d_in[13];
    const float* ws2       = (const float*)d_in[14];
    float* out = (float*)d_out;

    cudaFuncSetAttribute(flash_kernel, cudaFuncAttributeMaxDynamicSharedMemorySize, FA_SMEM_BYTES);

    float *p_xn, *p_qkv, *p_attn, *p_x2, *p_h, *p_s1, *p_s3, *p_sharedY, *p_gbuf, *p_ubuf;
    cudaGetSymbolAddress((void**)&p_xn, g_xn);
    cudaGetSymbolAddress((void**)&p_qkv, g_qkv);
    cudaGetSymbolAddress((void**)&p_attn, g_attn);
    cudaGetSymbolAddress((void**)&p_x2, g_x2);
    cudaGetSymbolAddress((void**)&p_h, g_h);
    cudaGetSymbolAddress((void**)&p_s1, g_s1);
    cudaGetSymbolAddress((void**)&p_s3, g_s3);
    cudaGetSymbolAddress((void**)&p_sharedY, g_sharedY);
    cudaGetSymbolAddress((void**)&p_gbuf, g_gbuf);
    cudaGetSymbolAddress((void**)&p_ubuf, g_ubuf);

    // attention block (fp32 front end — feeds routing)
    rmsnorm_kernel<<<TT, 256>>>(hidden, w_norm1, p_xn);
    sgemm_kernel<<<dim3(NQKV/128, TT/128), 256>>>(p_xn, wqkv, p_qkv, (const float*)0, NQKV, DD);
    ropek_kernel<<<dim3(TT, HKVn), 64>>>(p_qkv, positions);
    flash_kernel<<<dim3(TT/64, HQn), 256, FA_SMEM_BYTES>>>(p_qkv, positions, p_attn);
    sgemm_kernel<<<dim3(DD/128, TT/128), 256>>>(p_attn, wo, p_x2, hidden, DD, DD);

    // post-attn norm
    rmsnorm_kernel<<<TT, 256>>>(p_x2, w_norm2, p_h);

    // shared expert (tf32 tensor cores)
    tf32_gemm_kernel<<<dim3(FSn/128, TT/128, 1), 256>>>(p_h, ws1, p_s1, FSn, DD, 0);
    tf32_gemm_kernel<<<dim3(FSn/128, TT/128, 1), 256>>>(p_h, ws3, p_s3, FSn, DD, 0);
    silu_mul_kernel<<<(int)(((size_t)TT*FSn + 255)/256), 256>>>(p_s1, p_s3, p_s1, (size_t)TT*FSn);
    tf32_gemm_kernel<<<dim3(DD/128, TT/128, 1), 256>>>(p_s1, ws2, p_sharedY, DD, FSn, 0);

    // MoE routing (fp32, exact)
    zero_cnt_kernel<<<1, 32>>>();
    gate_route_kernel<<<TT, 128>>>(gate_w, gate_bias);
    scan_kernel<<<1, 1>>>();
    scatter_kernel<<<(PAIRS + 255)/256, 256>>>();

    // grouped expert GEMMs (tf32 tensor cores)
    tf32_gemm_kernel<<<dim3(Fn/128, PAIRS/128, En), 256>>>((const float*)0, w1, p_gbuf, Fn, DD, 1);
    tf32_gemm_kernel<<<dim3(Fn/128, PAIRS/128, En), 256>>>((const float*)0, w3, p_ubuf, Fn, DD, 1);
    silu_mul_moe_kernel<<<(int)(((size_t)PAIRS*Fn + 255)/256), 256>>>();
    tf32_gemm_kernel<<<dim3(DD/128, PAIRS/128, En), 256>>>((const float*)0, w2, (float*)0, DD, Fn, 2);

    // final combine
    combine_kernel<<<(int)(((size_t)TT*DD + 255)/256), 256>>>(out);
}

// round 13
// speedup vs baseline: 6.8080x; 1.2227x over previous
#include <cuda_runtime.h>
#include <math.h>
#include <stdint.h>

#define TT   2048
#define DD   2048
#define HQn  16
#define HKVn 8
#define HDn  128
#define En   16
#define Fn   1024
#define FSn  2048
#define NQKV 4096
#define PAIRS (TT*2)

__device__ float g_xn[(size_t)TT*DD];
__device__ float g_qkv[(size_t)TT*NQKV];
__device__ float g_attn[(size_t)TT*DD];
__device__ float g_x2[(size_t)TT*DD];
__device__ float g_h[(size_t)TT*DD];
__device__ float g_s1[(size_t)TT*FSn];
__device__ float g_s3[(size_t)TT*FSn];
__device__ float g_sharedY[(size_t)TT*DD];
__device__ float g_gbuf[(size_t)PAIRS*Fn];
__device__ float g_ubuf[(size_t)PAIRS*Fn];
__device__ float g_y[(size_t)PAIRS*DD];
__device__ float g_k2[(size_t)TT*HKVn*HDn];   // roped K, layout [t][kvh][d]
__device__ int   g_idx[PAIRS];
__device__ float g_wtk[PAIRS];
__device__ int   g_cnt[En];
__device__ int   g_off[En];
__device__ int   g_cur[En];
__device__ int   g_perm[PAIRS];

__device__ __forceinline__ float siluf(float x) { return x / (1.f + expf(-x)); }

// RoPE helper: pair index i (0..63), token t.
__device__ __forceinline__ void rope_cs(const int* __restrict__ p32, int t, int i,
                                        float& c, float& s) {
    int sec = (i < 22) ? 0 : ((i < 44) ? 1 : 2);
    bool is64 = (p32[1] == 0);
    int lin = sec * TT + t;
    float pos = (float)(is64 ? p32[2*lin] : p32[lin]);
    float invf = (float)exp(-((double)i / 64.0) * log(500000.0));
    sincosf(pos * invf, &s, &c);
}

__device__ __forceinline__ float to_tf32(float x) {
    uint32_t u;
    asm("cvt.rna.tf32.f32 %0, %1;" : "=r"(u) : "f"(x));
    return __uint_as_float(u);
}

__global__ void rmsnorm_kernel(const float* __restrict__ x, const float* __restrict__ w,
                               float* __restrict__ out) {
    int row = blockIdx.x;
    const float* xr = x + (size_t)row * DD;
    float* orow = out + (size_t)row * DD;
    float sum = 0.f;
    for (int i = threadIdx.x; i < DD; i += 256) { float v = xr[i]; sum = fmaf(v, v, sum); }
    __shared__ float red[8]; __shared__ float rinv;
    for (int o = 16; o > 0; o >>= 1) sum += __shfl_xor_sync(0xffffffffu, sum, o);
    if ((threadIdx.x & 31) == 0) red[threadIdx.x >> 5] = sum;
    __syncthreads();
    if (threadIdx.x == 0) {
        float s = 0.f;
        #pragma unroll
        for (int i = 0; i < 8; i++) s += red[i];
        rinv = rsqrtf(s / (float)DD + 1e-5f);
    }
    __syncthreads();
    float r = rinv;
    for (int i = threadIdx.x; i < DD; i += 256) orow[i] = xr[i] * r * w[i];
}

// ---------- out-of-place K rope: g_k2[t][kh][d] (PROVEN) ----------
__global__ void ropek_kernel(const float* __restrict__ qkv, const int* __restrict__ p32) {
    int t = blockIdx.x, kh = blockIdx.y, i = threadIdx.x;
    const float* src = qkv + (size_t)t * NQKV + HQn*HDn + kh * HDn;
    float c, s;
    rope_cs(p32, t, i, c, s);
    float x1 = src[2*i], x2 = src[2*i+1];
    float* dst = g_k2 + ((size_t)t * HKVn + kh) * HDn;
    dst[2*i]   = x1 * c - x2 * s;
    dst[2*i+1] = x2 * c + x1 * s;
}

// ---------- tiled flash attention: 64 q x 64 k tiles, K from g_k2, Q roped inline ----------
#define FA_SMEM_BYTES ((128*68*2 + 64*132 + 64*66 + 192) * 4)
__global__ void __launch_bounds__(256) flash_kernel(const float* __restrict__ qkv,
                                                    const int* __restrict__ p32,
                                                    float* __restrict__ attn) {
    extern __shared__ float sm[];
    float* Qt   = sm;                 // [hd=128][q 64+4] transposed, roped+scaled
    float* Kt   = Qt + 128*68;        // [hd=128][k 64+4] transposed (from g_k2)
    float* Vs   = Kt + 128*68;        // [k=64][hd 128+4]
    float* Ss   = Vs + 64*132;        // [q=64][k 64+2]
    float* mrow = Ss + 64*66;
    float* lrow = mrow + 64;
    float* arow = lrow + 64;
    const int qt = blockIdx.x, h = blockIdx.y;
    const int qbase = qt * 64;
    const int tid = threadIdx.x;
    const int tx = tid & 15, ty = tid >> 4;
    const float scale = 0.08838834764831845f;   // 1/sqrt(128)
    const int kvh = h >> 1;
    const int vcol = HQn*HDn + HKVn*HDn + kvh * HDn;

    for (int idx = tid; idx < 64*32; idx += 256) {
        int r = idx >> 5, c4 = (idx & 31) << 2;
        int t = qbase + r;
        float4 q4 = *(const float4*)&qkv[(size_t)t * NQKV + h*HDn + c4];
        float c0, s0, c1, s1;
        rope_cs(p32, t, c4/2,     c0, s0);
        rope_cs(p32, t, c4/2 + 1, c1, s1);
        Qt[(c4+0)*68 + r] = (q4.x * c0 - q4.y * s0) * scale;
        Qt[(c4+1)*68 + r] = (q4.y * c0 + q4.x * s0) * scale;
        Qt[(c4+2)*68 + r] = (q4.z * c1 - q4.w * s1) * scale;
        Qt[(c4+3)*68 + r] = (q4.w * c1 + q4.z * s1) * scale;
    }
    if (tid < 64) { mrow[tid] = -INFINITY; lrow[tid] = 0.f; }
    float o[4][8];
    #pragma unroll
    for (int i = 0; i < 4; i++)
        #pragma unroll
        for (int j = 0; j < 8; j++) o[i][j] = 0.f;

    for (int kt = 0; kt <= qt; kt++) {
        const int kbase = kt * 64;
        __syncthreads();
        for (int idx = tid; idx < 64*32; idx += 256) {
            int r = idx >> 5, c4 = (idx & 31) << 2;
            float4 k4 = *(const float4*)&g_k2[((size_t)(kbase + r) * HKVn + kvh) * HDn + c4];
            Kt[(c4+0)*68 + r] = k4.x;
            Kt[(c4+1)*68 + r] = k4.y;
            Kt[(c4+2)*68 + r] = k4.z;
            Kt[(c4+3)*68 + r] = k4.w;
            float4 v4 = *(const float4*)&qkv[(size_t)(kbase + r) * NQKV + vcol + c4];
            *(float4*)&Vs[r*132 + c4] = v4;
        }
        __syncthreads();
        float sacc[4][4];
        #pragma unroll
        for (int i = 0; i < 4; i++)
            #pragma unroll
            for (int c = 0; c < 4; c++) sacc[i][c] = 0.f;
        #pragma unroll 8
        for (int kk = 0; kk < 128; kk++) {
            float4 qa = *(const float4*)&Qt[kk*68 + ty*4];
            float4 kb = *(const float4*)&Kt[kk*68 + tx*4];
            float ra[4] = {qa.x,qa.y,qa.z,qa.w};
            float rb[4] = {kb.x,kb.y,kb.z,kb.w};
            #pragma unroll
            for (int i = 0; i < 4; i++)
                #pragma unroll
                for (int c = 0; c < 4; c++)
                    sacc[i][c] = fmaf(ra[i], rb[c], sacc[i][c]);
        }
        const bool diag = (kt == qt);
        #pragma unroll
        for (int i = 0; i < 4; i++) {
            int r = ty*4 + i;
            #pragma unroll
            for (int c = 0; c < 4; c++) {
                int cc = tx*4 + c;
                float v = sacc[i][c];
                if (diag && cc > r) v = -1e30f;
                Ss[r*66 + cc] = v;
            }
        }
        __syncthreads();
        {
            int r = tid >> 2, q = tid & 3;
            float m0 = mrow[r];
            float mx = m0;
            for (int j = q; j < 64; j += 4) mx = fmaxf(mx, Ss[r*66 + j]);
            mx = fmaxf(mx, __shfl_xor_sync(0xffffffffu, mx, 1));
            mx = fmaxf(mx, __shfl_xor_sync(0xffffffffu, mx, 2));
            float sum = 0.f;
            for (int j = q; j < 64; j += 4) {
                float p = expf(Ss[r*66 + j] - mx);
                Ss[r*66 + j] = p;
                sum += p;
            }
            sum += __shfl_xor_sync(0xffffffffu, sum, 1);
            sum += __shfl_xor_sync(0xffffffffu, sum, 2);
            if (q == 0) {
                float al = expf(m0 - mx);
                lrow[r] = lrow[r] * al + sum;
                mrow[r] = mx;
                arow[r] = al;
            }
        }
        __syncthreads();
        float av[4];
        #pragma unroll
        for (int i = 0; i < 4; i++) av[i] = arow[ty*4 + i];
        #pragma unroll
        for (int i = 0; i < 4; i++)
            #pragma unroll
            for (int j = 0; j < 8; j++) o[i][j] *= av[i];
        #pragma unroll 4
        for (int jk = 0; jk < 64; jk++) {
            float p0 = Ss[(ty*4+0)*66 + jk];
            float p1 = Ss[(ty*4+1)*66 + jk];
            float p2 = Ss[(ty*4+2)*66 + jk];
            float p3 = Ss[(ty*4+3)*66 + jk];
            float4 v0 = *(const float4*)&Vs[jk*132 + tx*8];
            float4 v1 = *(const float4*)&Vs[jk*132 + tx*8 + 4];
            float rv[8] = {v0.x,v0.y,v0.z,v0.w,v1.x,v1.y,v1.z,v1.w};
            #pragma unroll
            for (int j = 0; j < 8; j++) {
                o[0][j] = fmaf(p0, rv[j], o[0][j]);
                o[1][j] = fmaf(p1, rv[j], o[1][j]);
                o[2][j] = fmaf(p2, rv[j], o[2][j]);
                o[3][j] = fmaf(p3, rv[j], o[3][j]);
            }
        }
    }
    #pragma unroll
    for (int i = 0; i < 4; i++) {
        int r = ty*4 + i;
        float inv = 1.f / lrow[r];
        float* dst = attn + (size_t)(qbase + r) * DD + h*HDn + tx*8;
        *(float4*)dst     = make_float4(o[i][0]*inv, o[i][1]*inv, o[i][2]*inv, o[i][3]*inv);
        *(float4*)(dst+4) = make_float4(o[i][4]*inv, o[i][5]*inv, o[i][6]*inv, o[i][7]*inv);
    }
}

// ---------- tf32 tensor-core GEMM ----------
// mode 0: dense  C[r*N]        = A[r*K] @ B  (+ resid[r*N] if non-null)
// mode 1: moe-up C[(off+r)*N]  = g_h[perm[off+r]>>1] @ (B + e*K*N)
// mode 2: moe-dn g_y[perm*N]   = g_gbuf[(off+r)*K]   @ (B + e*K*N)
__global__ void __launch_bounds__(256) tf32_gemm_kernel(
    const float* __restrict__ A, const float* __restrict__ B, float* __restrict__ C,
    int N, int K, int mode, const float* __restrict__ resid) {
    __shared__ float As[128][36];
    __shared__ float Bs[32][136];
    const int tid = threadIdx.x;
    const int bx = blockIdx.x * 128, by = blockIdx.y * 128;
    int cnt = 1 << 30, off = 0;
    const float* Bp = B;
    if (mode != 0) {
        int e = blockIdx.z;
        cnt = g_cnt[e]; off = g_off[e];
        if (by >= cnt) return;
        Bp = B + (size_t)e * K * N;
    }
    const int arow = tid >> 1, acol = (tid & 1) * 16;
    const int gRow = by + arow;
    const bool av = gRow < cnt;
    const float* aptr = 0;
    if (mode == 0)           aptr = A + (size_t)gRow * K;
    else if (av && mode == 1) aptr = g_h + (size_t)(g_perm[off + gRow] >> 1) * DD;
    else if (av)             aptr = g_gbuf + (size_t)(off + gRow) * K;
    const int brow = tid >> 3, bcol = (tid & 7) * 16;

    float acc[4][4][4];
    #pragma unroll
    for (int mt = 0; mt < 4; mt++)
        #pragma unroll
        for (int nt = 0; nt < 4; nt++)
            #pragma unroll
            for (int z = 0; z < 4; z++) acc[mt][nt][z] = 0.f;

    const int warp = tid >> 5, lane = tid & 31;
    const int wm = (warp & 1) * 64, wn = (warp >> 1) * 32;
    const int g = lane >> 2, tg = lane & 3;

    for (int k0 = 0; k0 < K; k0 += 32) {
        #pragma unroll
        for (int j = 0; j < 4; j++) {
            float4 a4 = av ? *(const float4*)(aptr + k0 + acol + 4*j)
                           : make_float4(0.f,0.f,0.f,0.f);
            As[arow][acol+4*j+0] = to_tf32(a4.x);
            As[arow][acol+4*j+1] = to_tf32(a4.y);
            As[arow][acol+4*j+2] = to_tf32(a4.z);
            As[arow][acol+4*j+3] = to_tf32(a4.w);
            float4 b4 = *(const float4*)(Bp + (size_t)(k0 + brow) * N + bx + bcol + 4*j);
            Bs[brow][bcol+4*j+0] = to_tf32(b4.x);
            Bs[brow][bcol+4*j+1] = to_tf32(b4.y);
            Bs[brow][bcol+4*j+2] = to_tf32(b4.z);
            Bs[brow][bcol+4*j+3] = to_tf32(b4.w);
        }
        __syncthreads();
        #pragma unroll
        for (int kk = 0; kk < 32; kk += 8) {
            float af[4][4]; float bf[4][2];
            #pragma unroll
            for (int mt = 0; mt < 4; mt++) {
                int r0 = wm + mt*16 + g;
                af[mt][0] = As[r0][kk+tg];
                af[mt][1] = As[r0+8][kk+tg];
                af[mt][2] = As[r0][kk+tg+4];
                af[mt][3] = As[r0+8][kk+tg+4];
            }
            #pragma unroll
            for (int nt = 0; nt < 4; nt++) {
                int cc = wn + nt*8 + g;
                bf[nt][0] = Bs[kk+tg][cc];
                bf[nt][1] = Bs[kk+tg+4][cc];
            }
            #pragma unroll
            for (int mt = 0; mt < 4; mt++)
                #pragma unroll
                for (int nt = 0; nt < 4; nt++)
                    asm volatile(
                        "mma.sync.aligned.m16n8k8.row.col.f32.tf32.tf32.f32 "
                        "{%0,%1,%2,%3}, {%4,%5,%6,%7}, {%8,%9}, {%0,%1,%2,%3};"
                        : "+f"(acc[mt][nt][0]), "+f"(acc[mt][nt][1]),
                          "+f"(acc[mt][nt][2]), "+f"(acc[mt][nt][3])
                        : "r"(__float_as_uint(af[mt][0])), "r"(__float_as_uint(af[mt][1])),
                          "r"(__float_as_uint(af[mt][2])), "r"(__float_as_uint(af[mt][3])),
                          "r"(__float_as_uint(bf[nt][0])), "r"(__float_as_uint(bf[nt][1])));
        }
        __syncthreads();
    }
    #pragma unroll
    for (int mt = 0; mt < 4; mt++) {
        #pragma unroll
        for (int half = 0; half < 2; half++) {
            int r = by + wm + mt*16 + g + half*8;
            if (r >= cnt) continue;
            float* crow;
            if (mode == 0)      crow = C + (size_t)r * N;
            else if (mode == 1) crow = C + (size_t)(off + r) * N;
            else                crow = g_y + (size_t)g_perm[off + r] * N;
            #pragma unroll
            for (int nt = 0; nt < 4; nt++) {
                int cc = bx + wn + nt*8 + 2*tg;
                float v0 = acc[mt][nt][half*2+0];
                float v1 = acc[mt][nt][half*2+1];
                if (resid) {
                    v0 += resid[(size_t)r * N + cc];
                    v1 += resid[(size_t)r * N + cc + 1];
                }
                crow[cc]   = v0;
                crow[cc+1] = v1;
            }
        }
    }
}

__global__ void zero_cnt_kernel() { if (threadIdx.x < En) g_cnt[threadIdx.x] = 0; }

__global__ void gate_route_kernel(const float* __restrict__ gw, const float* __restrict__ gbias) {
    int t = blockIdx.x, tid = threadIdx.x;
    const float* hr = g_h + (size_t)t * DD;
    __shared__ float part[128];
    __shared__ float lg[En];
    int e = tid & 15, gdx = tid >> 4;
    float s = 0.f;
    for (int d = gdx; d < DD; d += 8) s = fmaf(hr[d], gw[d * En + e], s);
    part[tid] = s;
    __syncthreads();
    if (tid < En) {
        float l = 0.f;
        #pragma unroll
        for (int gg = 0; gg < 8; gg++) l += part[gg * 16 + tid];
        lg[tid] = l;
    }
    __syncthreads();
    if (tid == 0) {
        float mx = lg[0];
        for (int j = 1; j < En; j++) mx = fmaxf(mx, lg[j]);
        float prob[En]; float sum = 0.f;
        for (int j = 0; j < En; j++) { prob[j] = expf(lg[j] - mx); sum += prob[j]; }
        float inv = 1.f / sum;
        float sel[En];
        for (int j = 0; j < En; j++) { prob[j] *= inv; sel[j] = prob[j] + gbias[j]; }
        int i0 = 0; float b0 = sel[0];
        for (int j = 1; j < En; j++) if (sel[j] > b0) { b0 = sel[j]; i0 = j; }
        int i1 = -1; float b1 = -1e30f;
        for (int j = 0; j < En; j++) if (j != i0 && sel[j] > b1) { b1 = sel[j]; i1 = j; }
        float w0 = prob[i0], w1v = prob[i1], ws = w0 + w1v;
        g_idx[2*t]   = i0;      g_idx[2*t+1] = i1;
        g_wtk[2*t]   = w0 / ws; g_wtk[2*t+1] = w1v / ws;
        atomicAdd(&g_cnt[i0], 1);
        atomicAdd(&g_cnt[i1], 1);
    }
}

__global__ void scan_kernel() {
    int o = 0;
    for (int e = 0; e < En; e++) { g_off[e] = o; o += g_cnt[e]; g_cur[e] = 0; }
}

__global__ void scatter_kernel() {
    int p = blockIdx.x * 256 + threadIdx.x;
    if (p >= PAIRS) return;
    int e = g_idx[p];
    int pos = atomicAdd(&g_cur[e], 1);
    g_perm[g_off[e] + pos] = p;
}

__global__ void silu_mul_moe_kernel() {
    size_t i = (size_t)blockIdx.x * 256 + threadIdx.x;
    if (i >= (size_t)PAIRS * Fn) return;
    int ppos = (int)(i / Fn);
    int pair = g_perm[ppos];
    g_gbuf[i] = siluf(g_gbuf[i]) * g_ubuf[i] * g_wtk[pair];
}

__global__ void silu_mul_kernel(const float* __restrict__ a, const float* __restrict__ b,
                                float* __restrict__ o, size_t n) {
    size_t i = (size_t)blockIdx.x * 256 + threadIdx.x;
    if (i < n) o[i] = siluf(a[i]) * b[i];
}

__global__ void combine_kernel(float* __restrict__ out) {
    size_t i = (size_t)blockIdx.x * 256 + threadIdx.x;
    if (i >= (size_t)TT * DD) return;
    size_t t = i / DD, d = i % DD;
    out[i] = g_x2[i] + g_sharedY[i] + g_y[(2*t)*DD + d] + g_y[(2*t+1)*DD + d];
}

extern "C" void kernel_launch(void* const* d_in, const int* in_sizes, int n_in,
                              void* d_out, int out_size) {
    if (n_in != 15) return;
    if (in_sizes[0] != 3*TT) return;
    if (in_sizes[5] != DD*NQKV) return;
    if (in_sizes[7] != DD*En) return;
    if (in_sizes[8] != En) return;
    if (in_sizes[9] != (int)((size_t)En*DD*Fn)) return;

    const int*   positions = (const int*)d_in[0];
    const float* hidden    = (const float*)d_in[1];
    const float* w_norm1   = (const float*)d_in[3];
    const float* w_norm2   = (const float*)d_in[4];
    const float* wqkv      = (const float*)d_in[5];
    const float* wo        = (const float*)d_in[6];
    const float* gate_w    = (const float*)d_in[7];
    const float* gate_bias = (const float*)d_in[8];
    const float* w1        = (const float*)d_in[9];
    const float* w3        = (const float*)d_in[10];
    const float* w2        = (const float*)d_in[11];
    const float* ws1       = (const float*)d_in[12];
    const float* ws3       = (const float*)d_in[13];
    const float* ws2       = (const float*)d_in[14];
    float* out = (float*)d_out;

    cudaFuncSetAttribute(flash_kernel, cudaFuncAttributeMaxDynamicSharedMemorySize, FA_SMEM_BYTES);

    float *p_xn, *p_qkv, *p_attn, *p_x2, *p_h, *p_s1, *p_s3, *p_sharedY, *p_gbuf, *p_ubuf;
    cudaGetSymbolAddress((void**)&p_xn, g_xn);
    cudaGetSymbolAddress((void**)&p_qkv, g_qkv);
    cudaGetSymbolAddress((void**)&p_attn, g_attn);
    cudaGetSymbolAddress((void**)&p_x2, g_x2);
    cudaGetSymbolAddress((void**)&p_h, g_h);
    cudaGetSymbolAddress((void**)&p_s1, g_s1);
    cudaGetSymbolAddress((void**)&p_s3, g_s3);
    cudaGetSymbolAddress((void**)&p_sharedY, g_sharedY);
    cudaGetSymbolAddress((void**)&p_gbuf, g_gbuf);
    cudaGetSymbolAddress((void**)&p_ubuf, g_ubuf);

    // attention block (QKV + wo now tf32 tensor cores)
    rmsnorm_kernel<<<TT, 256>>>(hidden, w_norm1, p_xn);
    tf32_gemm_kernel<<<dim3(NQKV/128, TT/128, 1), 256>>>(p_xn, wqkv, p_qkv, NQKV, DD, 0, (const float*)0);
    ropek_kernel<<<dim3(TT, HKVn), 64>>>(p_qkv, positions);
    flash_kernel<<<dim3(TT/64, HQn), 256, FA_SMEM_BYTES>>>(p_qkv, positions, p_attn);
    tf32_gemm_kernel<<<dim3(DD/128, TT/128, 1), 256>>>(p_attn, wo, p_x2, DD, DD, 0, hidden);

    // post-attn norm
    rmsnorm_kernel<<<TT, 256>>>(p_x2, w_norm2, p_h);

    // shared expert (tf32)
    tf32_gemm_kernel<<<dim3(FSn/128, TT/128, 1), 256>>>(p_h, ws1, p_s1, FSn, DD, 0, (const float*)0);
    tf32_gemm_kernel<<<dim3(FSn/128, TT/128, 1), 256>>>(p_h, ws3, p_s3, FSn, DD, 0, (const float*)0);
    silu_mul_kernel<<<(int)(((size_t)TT*FSn + 255)/256), 256>>>(p_s1, p_s3, p_s1, (size_t)TT*FSn);
    tf32_gemm_kernel<<<dim3(DD/128, TT/128, 1), 256>>>(p_s1, ws2, p_sharedY, DD, FSn, 0, (const float*)0);

    // MoE routing (fp32, exact)
    zero_cnt_kernel<<<1, 32>>>();
    gate_route_kernel<<<TT, 128>>>(gate_w, gate_bias);
    scan_kernel<<<1, 1>>>();
    scatter_kernel<<<(PAIRS + 255)/256, 256>>>();

    // grouped expert GEMMs (tf32)
    tf32_gemm_kernel<<<dim3(Fn/128, PAIRS/128, En), 256>>>((const float*)0, w1, p_gbuf, Fn, DD, 1, (const float*)0);
    tf32_gemm_kernel<<<dim3(Fn/128, PAIRS/128, En), 256>>>((const float*)0, w3, p_ubuf, Fn, DD, 1, (const float*)0);
    silu_mul_moe_kernel<<<(int)(((size_t)PAIRS*Fn + 255)/256), 256>>>();
    tf32_gemm_kernel<<<dim3(DD/128, PAIRS/128, En), 256>>>((const float*)0, w2, (float*)0, DD, Fn, 2, (const float*)0);

    // final combine
    combine_kernel<<<(int)(((size_t)TT*DD + 255)/256), 256>>>(out);
}

// round 16
// speedup vs baseline: 7.6571x; 1.1247x over previous
#include <cuda_runtime.h>
#include <math.h>
#include <stdint.h>

#define TT   2048
#define DD   2048
#define HQn  16
#define HKVn 8
#define HDn  128
#define En   16
#define Fn   1024
#define FSn  2048
#define NQKV 4096
#define PAIRS (TT*2)

__device__ float g_xn[(size_t)TT*DD];
__device__ float g_qkv[(size_t)TT*NQKV];
__device__ float g_attn[(size_t)TT*DD];
__device__ float g_x2[(size_t)TT*DD];
__device__ float g_h[(size_t)TT*DD];
__device__ float g_s1[(size_t)TT*FSn];
__device__ float g_s3[(size_t)TT*FSn];
__device__ float g_sharedY[(size_t)TT*DD];
__device__ float g_gbuf[(size_t)PAIRS*Fn];
__device__ float g_ubuf[(size_t)PAIRS*Fn];
__device__ float g_y[(size_t)PAIRS*DD];
__device__ float g_k2[(size_t)TT*HKVn*HDn];   // roped K, layout [t][kvh][d]
__device__ int   g_idx[PAIRS];
__device__ float g_wtk[PAIRS];
__device__ int   g_cnt[En];
__device__ int   g_off[En];
__device__ int   g_cur[En];
__device__ int   g_perm[PAIRS];

__device__ __forceinline__ float siluf(float x) { return x / (1.f + expf(-x)); }

__device__ __forceinline__ void rope_cs(const int* __restrict__ p32, int t, int i,
                                        float& c, float& s) {
    int sec = (i < 22) ? 0 : ((i < 44) ? 1 : 2);
    bool is64 = (p32[1] == 0);
    int lin = sec * TT + t;
    float pos = (float)(is64 ? p32[2*lin] : p32[lin]);
    float invf = (float)exp(-((double)i / 64.0) * log(500000.0));
    sincosf(pos * invf, &s, &c);
}

__device__ __forceinline__ uint32_t tf32_bits(float x) {
    uint32_t u;
    asm("cvt.rna.tf32.f32 %0, %1;" : "=r"(u) : "f"(x));
    return u;
}

__device__ __forceinline__ void cp_async16(void* smem, const void* gmem, bool valid) {
    uint32_t s = (uint32_t)__cvta_generic_to_shared(smem);
    int sz = valid ? 16 : 0;
    asm volatile("cp.async.cg.shared.global [%0], [%1], 16, %2;" :: "r"(s), "l"(gmem), "r"(sz));
}

__global__ void rmsnorm_kernel(const float* __restrict__ x, const float* __restrict__ w,
                               float* __restrict__ out) {
    int row = blockIdx.x;
    const float* xr = x + (size_t)row * DD;
    float* orow = out + (size_t)row * DD;
    float sum = 0.f;
    for (int i = threadIdx.x; i < DD; i += 256) { float v = xr[i]; sum = fmaf(v, v, sum); }
    __shared__ float red[8]; __shared__ float rinv;
    for (int o = 16; o > 0; o >>= 1) sum += __shfl_xor_sync(0xffffffffu, sum, o);
    if ((threadIdx.x & 31) == 0) red[threadIdx.x >> 5] = sum;
    __syncthreads();
    if (threadIdx.x == 0) {
        float s = 0.f;
        #pragma unroll
        for (int i = 0; i < 8; i++) s += red[i];
        rinv = rsqrtf(s / (float)DD + 1e-5f);
    }
    __syncthreads();
    float r = rinv;
    for (int i = threadIdx.x; i < DD; i += 256) orow[i] = xr[i] * r * w[i];
}

// ---------- out-of-place K rope: g_k2[t][kh][d] (PROVEN) ----------
__global__ void ropek_kernel(const float* __restrict__ qkv, const int* __restrict__ p32) {
    int t = blockIdx.x, kh = blockIdx.y, i = threadIdx.x;
    const float* src = qkv + (size_t)t * NQKV + HQn*HDn + kh * HDn;
    float c, s;
    rope_cs(p32, t, i, c, s);
    float x1 = src[2*i], x2 = src[2*i+1];
    float* dst = g_k2 + ((size_t)t * HKVn + kh) * HDn;
    dst[2*i]   = x1 * c - x2 * s;
    dst[2*i+1] = x2 * c + x1 * s;
}

// ---------- tiled flash attention (unchanged, proven) ----------
#define FA_SMEM_BYTES ((128*68*2 + 64*132 + 64*66 + 192) * 4)
__global__ void __launch_bounds__(256) flash_kernel(const float* __restrict__ qkv,
                                                    const int* __restrict__ p32,
                                                    float* __restrict__ attn) {
    extern __shared__ float sm[];
    float* Qt   = sm;
    float* Kt   = Qt + 128*68;
    float* Vs   = Kt + 128*68;
    float* Ss   = Vs + 64*132;
    float* mrow = Ss + 64*66;
    float* lrow = mrow + 64;
    float* arow = lrow + 64;
    const int qt = blockIdx.x, h = blockIdx.y;
    const int qbase = qt * 64;
    const int tid = threadIdx.x;
    const int tx = tid & 15, ty = tid >> 4;
    const float scale = 0.08838834764831845f;
    const int kvh = h >> 1;
    const int vcol = HQn*HDn + HKVn*HDn + kvh * HDn;

    for (int idx = tid; idx < 64*32; idx += 256) {
        int r = idx >> 5, c4 = (idx & 31) << 2;
        int t = qbase + r;
        float4 q4 = *(const float4*)&qkv[(size_t)t * NQKV + h*HDn + c4];
        float c0, s0, c1, s1;
        rope_cs(p32, t, c4/2,     c0, s0);
        rope_cs(p32, t, c4/2 + 1, c1, s1);
        Qt[(c4+0)*68 + r] = (q4.x * c0 - q4.y * s0) * scale;
        Qt[(c4+1)*68 + r] = (q4.y * c0 + q4.x * s0) * scale;
        Qt[(c4+2)*68 + r] = (q4.z * c1 - q4.w * s1) * scale;
        Qt[(c4+3)*68 + r] = (q4.w * c1 + q4.z * s1) * scale;
    }
    if (tid < 64) { mrow[tid] = -INFINITY; lrow[tid] = 0.f; }
    float o[4][8];
    #pragma unroll
    for (int i = 0; i < 4; i++)
        #pragma unroll
        for (int j = 0; j < 8; j++) o[i][j] = 0.f;

    for (int kt = 0; kt <= qt; kt++) {
        const int kbase = kt * 64;
        __syncthreads();
        for (int idx = tid; idx < 64*32; idx += 256) {
            int r = idx >> 5, c4 = (idx & 31) << 2;
            float4 k4 = *(const float4*)&g_k2[((size_t)(kbase + r) * HKVn + kvh) * HDn + c4];
            Kt[(c4+0)*68 + r] = k4.x;
            Kt[(c4+1)*68 + r] = k4.y;
            Kt[(c4+2)*68 + r] = k4.z;
            Kt[(c4+3)*68 + r] = k4.w;
            float4 v4 = *(const float4*)&qkv[(size_t)(kbase + r) * NQKV + vcol + c4];
            *(float4*)&Vs[r*132 + c4] = v4;
        }
        __syncthreads();
        float sacc[4][4];
        #pragma unroll
        for (int i = 0; i < 4; i++)
            #pragma unroll
            for (int c = 0; c < 4; c++) sacc[i][c] = 0.f;
        #pragma unroll 8
        for (int kk = 0; kk < 128; kk++) {
            float4 qa = *(const float4*)&Qt[kk*68 + ty*4];
            float4 kb = *(const float4*)&Kt[kk*68 + tx*4];
            float ra[4] = {qa.x,qa.y,qa.z,qa.w};
            float rb[4] = {kb.x,kb.y,kb.z,kb.w};
            #pragma unroll
            for (int i = 0; i < 4; i++)
                #pragma unroll
                for (int c = 0; c < 4; c++)
                    sacc[i][c] = fmaf(ra[i], rb[c], sacc[i][c]);
        }
        const bool diag = (kt == qt);
        #pragma unroll
        for (int i = 0; i < 4; i++) {
            int r = ty*4 + i;
            #pragma unroll
            for (int c = 0; c < 4; c++) {
                int cc = tx*4 + c;
                float v = sacc[i][c];
                if (diag && cc > r) v = -1e30f;
                Ss[r*66 + cc] = v;
            }
        }
        __syncthreads();
        {
            int r = tid >> 2, q = tid & 3;
            float m0 = mrow[r];
            float mx = m0;
            for (int j = q; j < 64; j += 4) mx = fmaxf(mx, Ss[r*66 + j]);
            mx = fmaxf(mx, __shfl_xor_sync(0xffffffffu, mx, 1));
            mx = fmaxf(mx, __shfl_xor_sync(0xffffffffu, mx, 2));
            float sum = 0.f;
            for (int j = q; j < 64; j += 4) {
                float p = expf(Ss[r*66 + j] - mx);
                Ss[r*66 + j] = p;
                sum += p;
            }
            sum += __shfl_xor_sync(0xffffffffu, sum, 1);
            sum += __shfl_xor_sync(0xffffffffu, sum, 2);
            if (q == 0) {
                float al = expf(m0 - mx);
                lrow[r] = lrow[r] * al + sum;
                mrow[r] = mx;
                arow[r] = al;
            }
        }
        __syncthreads();
        float av[4];
        #pragma unroll
        for (int i = 0; i < 4; i++) av[i] = arow[ty*4 + i];
        #pragma unroll
        for (int i = 0; i < 4; i++)
            #pragma unroll
            for (int j = 0; j < 8; j++) o[i][j] *= av[i];
        #pragma unroll 4
        for (int jk = 0; jk < 64; jk++) {
            float p0 = Ss[(ty*4+0)*66 + jk];
            float p1 = Ss[(ty*4+1)*66 + jk];
            float p2 = Ss[(ty*4+2)*66 + jk];
            float p3 = Ss[(ty*4+3)*66 + jk];
            float4 v0 = *(const float4*)&Vs[jk*132 + tx*8];
            float4 v1 = *(const float4*)&Vs[jk*132 + tx*8 + 4];
            float rv[8] = {v0.x,v0.y,v0.z,v0.w,v1.x,v1.y,v1.z,v1.w};
            #pragma unroll
            for (int j = 0; j < 8; j++) {
                o[0][j] = fmaf(p0, rv[j], o[0][j]);
                o[1][j] = fmaf(p1, rv[j], o[1][j]);
                o[2][j] = fmaf(p2, rv[j], o[2][j]);
                o[3][j] = fmaf(p3, rv[j], o[3][j]);
            }
        }
    }
    #pragma unroll
    for (int i = 0; i < 4; i++) {
        int r = ty*4 + i;
        float inv = 1.f / lrow[r];
        float* dst = attn + (size_t)(qbase + r) * DD + h*HDn + tx*8;
        *(float4*)dst     = make_float4(o[i][0]*inv, o[i][1]*inv, o[i][2]*inv, o[i][3]*inv);
        *(float4*)(dst+4) = make_float4(o[i][4]*inv, o[i][5]*inv, o[i][6]*inv, o[i][7]*inv);
    }
}

// ---------- tf32 tensor-core GEMM, cp.async double-buffered, cvt in fragment load ----------
// mode 0: dense  C[r*N]        = A[r*K] @ B  (+ resid[r*N] if non-null)
// mode 1: moe-up C[(off+r)*N]  = g_h[perm[off+r]>>1] @ (B + e*K*N)
// mode 2: moe-dn g_y[perm*N]   = g_gbuf[(off+r)*K]   @ (B + e*K*N)
#define GEMM_SMEM_BYTES ((2*128*36 + 2*32*136) * 4)   // 71680
__global__ void __launch_bounds__(256) tf32_gemm_kernel(
    const float* __restrict__ A, const float* __restrict__ B, float* __restrict__ C,
    int N, int K, int mode, const float* __restrict__ resid) {
    extern __shared__ float smc[];
    float (*As)[128][36] = (float (*)[128][36])smc;
    float (*Bs)[32][136] = (float (*)[32][136])(smc + 2*128*36);
    const int tid = threadIdx.x;
    const int bx = blockIdx.x * 128, by = blockIdx.y * 128;
    int cnt = 1 << 30, off = 0;
    const float* Bp = B;
    if (mode != 0) {
        int e = blockIdx.z;
        cnt = g_cnt[e]; off = g_off[e];
        if (by >= cnt) return;
        Bp = B + (size_t)e * K * N;
    }
    const int arow = tid >> 1, acol = (tid & 1) * 16;
    const int gRow = by + arow;
    const bool av = gRow < cnt;
    const float* aptr;
    if (mode == 0)      aptr = A + (size_t)gRow * K;
    else if (!av)       aptr = g_h;   // dummy valid pointer; zero-filled via size-0 cp
    else if (mode == 1) aptr = g_h + (size_t)(g_perm[off + gRow] >> 1) * DD;
    else                aptr = g_gbuf + (size_t)(off + gRow) * K;
    const int brow = tid >> 3, bcol = (tid & 7) * 16;

    float acc[4][4][4];
    #pragma unroll
    for (int mt = 0; mt < 4; mt++)
        #pragma unroll
        for (int nt = 0; nt < 4; nt++)
            #pragma unroll
            for (int z = 0; z < 4; z++) acc[mt][nt][z] = 0.f;

    const int warp = tid >> 5, lane = tid & 31;
    const int wm = (warp & 1) * 64, wn = (warp >> 1) * 32;
    const int g = lane >> 2, tg = lane & 3;

    // prologue: stage 0
    #pragma unroll
    for (int j = 0; j < 4; j++) {
        cp_async16(&As[0][arow][acol + 4*j], aptr + acol + 4*j, av);
        cp_async16(&Bs[0][brow][bcol + 4*j], Bp + (size_t)brow * N + bx + bcol + 4*j, true);
    }
    asm volatile("cp.async.commit_group;");

    int buf = 0;
    for (int k0 = 0; k0 < K; k0 += 32) {
        if (k0 + 32 < K) {
            int nb = buf ^ 1;
            #pragma unroll
            for (int j = 0; j < 4; j++) {
                cp_async16(&As[nb][arow][acol + 4*j], aptr + k0 + 32 + acol + 4*j, av);
                cp_async16(&Bs[nb][brow][bcol + 4*j],
                           Bp + (size_t)(k0 + 32 + brow) * N + bx + bcol + 4*j, true);
            }
        }
        asm volatile("cp.async.commit_group;");
        asm volatile("cp.async.wait_group 1;");
        __syncthreads();

        #pragma unroll
        for (int kk = 0; kk < 32; kk += 8) {
            uint32_t af[4][4]; uint32_t bf[4][2];
            #pragma unroll
            for (int mt = 0; mt < 4; mt++) {
                int r0 = wm + mt*16 + g;
                af[mt][0] = tf32_bits(As[buf][r0][kk+tg]);
                af[mt][1] = tf32_bits(As[buf][r0+8][kk+tg]);
                af[mt][2] = tf32_bits(As[buf][r0][kk+tg+4]);
                af[mt][3] = tf32_bits(As[buf][r0+8][kk+tg+4]);
            }
            #pragma unroll
            for (int nt = 0; nt < 4; nt++) {
                int cc = wn + nt*8 + g;
                bf[nt][0] = tf32_bits(Bs[buf][kk+tg][cc]);
                bf[nt][1] = tf32_bits(Bs[buf][kk+tg+4][cc]);
            }
            #pragma unroll
            for (int mt = 0; mt < 4; mt++)
                #pragma unroll
                for (int nt = 0; nt < 4; nt++)
                    asm volatile(
                        "mma.sync.aligned.m16n8k8.row.col.f32.tf32.tf32.f32 "
                        "{%0,%1,%2,%3}, {%4,%5,%6,%7}, {%8,%9}, {%0,%1,%2,%3};"
                        : "+f"(acc[mt][nt][0]), "+f"(acc[mt][nt][1]),
                          "+f"(acc[mt][nt][2]), "+f"(acc[mt][nt][3])
                        : "r"(af[mt][0]), "r"(af[mt][1]),
                          "r"(af[mt][2]), "r"(af[mt][3]),
                          "r"(bf[nt][0]), "r"(bf[nt][1]));
        }
        buf ^= 1;
        __syncthreads();
    }

    #pragma unroll
    for (int mt = 0; mt < 4; mt++) {
        #pragma unroll
        for (int half = 0; half < 2; half++) {
            int r = by + wm + mt*16 + g + half*8;
            if (r >= cnt) continue;
            float* crow;
            if (mode == 0)      crow = C + (size_t)r * N;
            else if (mode == 1) crow = C + (size_t)(off + r) * N;
            else                crow = g_y + (size_t)g_perm[off + r] * N;
            #pragma unroll
            for (int nt = 0; nt < 4; nt++) {
                int cc = bx + wn + nt*8 + 2*tg;
                float v0 = acc[mt][nt][half*2+0];
                float v1 = acc[mt][nt][half*2+1];
                if (resid) {
                    v0 += resid[(size_t)r * N + cc];
                    v1 += resid[(size_t)r * N + cc + 1];
                }
                crow[cc]   = v0;
                crow[cc+1] = v1;
            }
        }
    }
}

__global__ void zero_cnt_kernel() { if (threadIdx.x < En) g_cnt[threadIdx.x] = 0; }

__global__ void gate_route_kernel(const float* __restrict__ gw, const float* __restrict__ gbias) {
    int t = blockIdx.x, tid = threadIdx.x;
    const float* hr = g_h + (size_t)t * DD;
    __shared__ float part[128];
    __shared__ float lg[En];
    int e = tid & 15, gdx = tid >> 4;
    float s = 0.f;
    for (int d = gdx; d < DD; d += 8) s = fmaf(hr[d], gw[d * En + e], s);
    part[tid] = s;
    __syncthreads();
    if (tid < En) {
        float l = 0.f;
        #pragma unroll
        for (int gg = 0; gg < 8; gg++) l += part[gg * 16 + tid];
        lg[tid] = l;
    }
    __syncthreads();
    if (tid == 0) {
        float mx = lg[0];
        for (int j = 1; j < En; j++) mx = fmaxf(mx, lg[j]);
        float prob[En]; float sum = 0.f;
        for (int j = 0; j < En; j++) { prob[j] = expf(lg[j] - mx); sum += prob[j]; }
        float inv = 1.f / sum;
        float sel[En];
        for (int j = 0; j < En; j++) { prob[j] *= inv; sel[j] = prob[j] + gbias[j]; }
        int i0 = 0; float b0 = sel[0];
        for (int j = 1; j < En; j++) if (sel[j] > b0) { b0 = sel[j]; i0 = j; }
        int i1 = -1; float b1 = -1e30f;
        for (int j = 0; j < En; j++) if (j != i0 && sel[j] > b1) { b1 = sel[j]; i1 = j; }
        float w0 = prob[i0], w1v = prob[i1], ws = w0 + w1v;
        g_idx[2*t]   = i0;      g_idx[2*t+1] = i1;
        g_wtk[2*t]   = w0 / ws; g_wtk[2*t+1] = w1v / ws;
        atomicAdd(&g_cnt[i0], 1);
        atomicAdd(&g_cnt[i1], 1);
    }
}

__global__ void scan_kernel() {
    int o = 0;
    for (int e = 0; e < En; e++) { g_off[e] = o; o += g_cnt[e]; g_cur[e] = 0; }
}

__global__ void scatter_kernel() {
    int p = blockIdx.x * 256 + threadIdx.x;
    if (p >= PAIRS) return;
    int e = g_idx[p];
    int pos = atomicAdd(&g_cur[e], 1);
    g_perm[g_off[e] + pos] = p;
}

__global__ void silu_mul_moe_kernel() {
    size_t i = (size_t)blockIdx.x * 256 + threadIdx.x;
    if (i >= (size_t)PAIRS * Fn) return;
    int ppos = (int)(i / Fn);
    int pair = g_perm[ppos];
    g_gbuf[i] = siluf(g_gbuf[i]) * g_ubuf[i] * g_wtk[pair];
}

__global__ void silu_mul_kernel(const float* __restrict__ a, const float* __restrict__ b,
                                float* __restrict__ o, size_t n) {
    size_t i = (size_t)blockIdx.x * 256 + threadIdx.x;
    if (i < n) o[i] = siluf(a[i]) * b[i];
}

__global__ void combine_kernel(float* __restrict__ out) {
    size_t i = (size_t)blockIdx.x * 256 + threadIdx.x;
    if (i >= (size_t)TT * DD) return;
    size_t t = i / DD, d = i % DD;
    out[i] = g_x2[i] + g_sharedY[i] + g_y[(2*t)*DD + d] + g_y[(2*t+1)*DD + d];
}

extern "C" void kernel_launch(void* const* d_in, const int* in_sizes, int n_in,
                              void* d_out, int out_size) {
    if (n_in != 15) return;
    if (in_sizes[0] != 3*TT) return;
    if (in_sizes[5] != DD*NQKV) return;
    if (in_sizes[7] != DD*En) return;
    if (in_sizes[8] != En) return;
    if (in_sizes[9] != (int)((size_t)En*DD*Fn)) return;

    const int*   positions = (const int*)d_in[0];
    const float* hidden    = (const float*)d_in[1];
    const float* w_norm1   = (const float*)d_in[3];
    const float* w_norm2   = (const float*)d_in[4];
    const float* wqkv      = (const float*)d_in[5];
    const float* wo        = (const float*)d_in[6];
    const float* gate_w    = (const float*)d_in[7];
    const float* gate_bias = (const float*)d_in[8];
    const float* w1        = (const float*)d_in[9];
    const float* w3        = (const float*)d_in[10];
    const float* w2        = (const float*)d_in[11];
    const float* ws1       = (const float*)d_in[12];
    const float* ws3       = (const float*)d_in[13];
    const float* ws2       = (const float*)d_in[14];
    float* out = (float*)d_out;

    cudaFuncSetAttribute(flash_kernel, cudaFuncAttributeMaxDynamicSharedMemorySize, FA_SMEM_BYTES);
    cudaFuncSetAttribute(tf32_gemm_kernel, cudaFuncAttributeMaxDynamicSharedMemorySize, GEMM_SMEM_BYTES);

    float *p_xn, *p_qkv, *p_attn, *p_x2, *p_h, *p_s1, *p_s3, *p_sharedY, *p_gbuf, *p_ubuf;
    cudaGetSymbolAddress((void**)&p_xn, g_xn);
    cudaGetSymbolAddress((void**)&p_qkv, g_qkv);
    cudaGetSymbolAddress((void**)&p_attn, g_attn);
    cudaGetSymbolAddress((void**)&p_x2, g_x2);
    cudaGetSymbolAddress((void**)&p_h, g_h);
    cudaGetSymbolAddress((void**)&p_s1, g_s1);
    cudaGetSymbolAddress((void**)&p_s3, g_s3);
    cudaGetSymbolAddress((void**)&p_sharedY, g_sharedY);
    cudaGetSymbolAddress((void**)&p_gbuf, g_gbuf);
    cudaGetSymbolAddress((void**)&p_ubuf, g_ubuf);

    // attention block
    rmsnorm_kernel<<<TT, 256>>>(hidden, w_norm1, p_xn);
    tf32_gemm_kernel<<<dim3(NQKV/128, TT/128, 1), 256, GEMM_SMEM_BYTES>>>(p_xn, wqkv, p_qkv, NQKV, DD, 0, (const float*)0);
    ropek_kernel<<<dim3(TT, HKVn), 64>>>(p_qkv, positions);
    flash_kernel<<<dim3(TT/64, HQn), 256, FA_SMEM_BYTES>>>(p_qkv, positions, p_attn);
    tf32_gemm_kernel<<<dim3(DD/128, TT/128, 1), 256, GEMM_SMEM_BYTES>>>(p_attn, wo, p_x2, DD, DD, 0, hidden);

    // post-attn norm
    rmsnorm_kernel<<<TT, 256>>>(p_x2, w_norm2, p_h);

    // shared expert
    tf32_gemm_kernel<<<dim3(FSn/128, TT/128, 1), 256, GEMM_SMEM_BYTES>>>(p_h, ws1, p_s1, FSn, DD, 0, (const float*)0);
    tf32_gemm_kernel<<<dim3(FSn/128, TT/128, 1), 256, GEMM_SMEM_BYTES>>>(p_h, ws3, p_s3, FSn, DD, 0, (const float*)0);
    silu_mul_kernel<<<(int)(((size_t)TT*FSn + 255)/256), 256>>>(p_s1, p_s3, p_s1, (size_t)TT*FSn);
    tf32_gemm_kernel<<<dim3(DD/128, TT/128, 1), 256, GEMM_SMEM_BYTES>>>(p_s1, ws2, p_sharedY, DD, FSn, 0, (const float*)0);

    // MoE routing (fp32, exact)
    zero_cnt_kernel<<<1, 32>>>();
    gate_route_kernel<<<TT, 128>>>(gate_w, gate_bias);
    scan_kernel<<<1, 1>>>();
    scatter_kernel<<<(PAIRS + 255)/256, 256>>>();

    // grouped expert GEMMs
    tf32_gemm_kernel<<<dim3(Fn/128, PAIRS/128, En), 256, GEMM_SMEM_BYTES>>>((const float*)0, w1, p_gbuf, Fn, DD, 1, (const float*)0);
    tf32_gemm_kernel<<<dim3(Fn/128, PAIRS/128, En), 256, GEMM_SMEM_BYTES>>>((const float*)0, w3, p_ubuf, Fn, DD, 1, (const float*)0);
    silu_mul_moe_kernel<<<(int)(((size_t)PAIRS*Fn + 255)/256), 256>>>();
    tf32_gemm_kernel<<<dim3(DD/128, PAIRS/128, En), 256, GEMM_SMEM_BYTES>>>((const float*)0, w2, (float*)0, DD, Fn, 2, (const float*)0);

    // final combine
    combine_kernel<<<(int)(((size_t)TT*DD + 255)/256), 256>>>(out);
}